// round 12
// baseline (speedup 1.0000x reference)
#include <cuda_runtime.h>
#include <cuda_fp16.h>
#include <cstdint>
#include <math.h>

#define D_MODEL 1024
#define NH 16
#define DK 64
#define BAND 100
#define BB 2
#define SS 2048
#define M_TOT (BB * SS)
#define DM2 (D_MODEL * D_MODEL)

// ---------------- scratch (device globals; no allocs allowed) ----------------
__device__ __align__(256) __half g_qh[BB * NH * SS * DK];   // Q hi (scaled 0.125)
__device__ __align__(256) __half g_ql[BB * NH * SS * DK];   // Q lo
__device__ __align__(256) __half g_kh[BB * NH * SS * DK];   // K single
__device__ __align__(256) __half g_vh[BB * NH * SS * DK];   // V single
__device__ __align__(256) __half g_xh[M_TOT * D_MODEL];     // x hi
__device__ __align__(256) __half g_xl[M_TOT * D_MODEL];     // x lo
__device__ __align__(256) __half g_wh[4 * DM2];             // W single (4 slots)
__device__ __align__(256) __half g_aoh[M_TOT * D_MODEL];    // attn out (single fp16)

// ---------------- helpers ----------------
__device__ __forceinline__ uint32_t s2u(const void* p) {
    uint32_t a;
    asm("{ .reg .u64 t; cvta.to.shared.u64 t, %1; cvt.u32.u64 %0, t; }" : "=r"(a) : "l"(p));
    return a;
}

#define SWZ64(o)  ((o) ^ (((o) >> 3) & 0x30))
#define SWZ128(o) ((o) ^ (((o) >> 3) & 0x70))

#define CP16(dst, src) \
    asm volatile("cp.async.cg.shared.global [%0], [%1], 16;" :: "r"(dst), "l"(src))
#define CP_COMMIT() asm volatile("cp.async.commit_group;" ::: "memory")

#define LDSM4(r, addr) \
    asm volatile("ldmatrix.sync.aligned.m8n8.x4.shared.b16 {%0,%1,%2,%3}, [%4];" \
                 : "=r"((r)[0]), "=r"((r)[1]), "=r"((r)[2]), "=r"((r)[3]) : "r"(addr))
#define LDSM4T(r, addr) \
    asm volatile("ldmatrix.sync.aligned.m8n8.x4.trans.shared.b16 {%0,%1,%2,%3}, [%4];" \
                 : "=r"((r)[0]), "=r"((r)[1]), "=r"((r)[2]), "=r"((r)[3]) : "r"(addr))

#define MMAH(d, a, bx, by) \
    asm volatile("mma.sync.aligned.m16n8k16.row.col.f32.f16.f16.f32 " \
                 "{%0,%1,%2,%3}, {%4,%5,%6,%7}, {%8,%9}, {%0,%1,%2,%3};" \
                 : "+f"((d)[0]), "+f"((d)[1]), "+f"((d)[2]), "+f"((d)[3]) \
                 : "r"((a)[0]), "r"((a)[1]), "r"((a)[2]), "r"((a)[3]), "r"(bx), "r"(by))

__device__ __forceinline__ uint32_t pack2h(float a, float b, uint32_t& lo) {
    __half2 h = __floats2half2_rn(a, b);
    __half2 l = __floats2half2_rn(a - __low2float(h), b - __high2float(h));
    lo = *reinterpret_cast<uint32_t*>(&l);
    return *reinterpret_cast<uint32_t*>(&h);
}
__device__ __forceinline__ uint32_t pack2s(float a, float b) {
    __half2 h = __floats2half2_rn(a, b);
    return *reinterpret_cast<uint32_t*>(&h);
}

// ---------------- fp32 -> fp16 conversions (single launch) ----------------
#define NX4 (M_TOT * D_MODEL / 4)
#define NW4 (DM2 / 4)

__global__ void cvt_all(const float4* __restrict__ x,
                        const float4* __restrict__ wq, const float4* __restrict__ wk,
                        const float4* __restrict__ wv, const float4* __restrict__ wo)
{
    int i = blockIdx.x * blockDim.x + threadIdx.x;
    if (i < NX4) {
        float4 v = x[i];
        uint2 hv, lv;
        hv.x = pack2h(v.x, v.y, lv.x);
        hv.y = pack2h(v.z, v.w, lv.y);
        ((uint2*)g_xh)[i] = hv;
        ((uint2*)g_xl)[i] = lv;
    } else {
        int j = i - NX4;
        if (j >= 4 * NW4) return;
        int slot = j >> 18;
        int k = j & (NW4 - 1);
        const float4* src = (slot == 0) ? wq : (slot == 1) ? wk : (slot == 2) ? wv : wo;
        float4 v = src[k];
        uint2 hv;
        hv.x = pack2s(v.x, v.y);
        hv.y = pack2s(v.z, v.w);
        ((uint2*)g_wh)[j] = hv;
    }
}

// ---------------------------------------------------------------------------
// HMMA fp16 GEMM. CTA 128x128, 8 warps (4M x 2N, warp tile 32x64),
// K-chunk 32, cp.async 3-stage, 256 threads, 2 CTAs/SM (16 warps/SM).
// two_terms (Q proj only): D = (Ah+Al) @ W^T; else D = Ah @ W^T.
// stage (24KB): Ah[128x64B]@0  Al@8192  Bh[128x64B]@16384
// ---------------------------------------------------------------------------
__global__ __launch_bounds__(256, 2) void tc_gemm(
    int mode, const float* __restrict__ b0, const float* __restrict__ b1,
    const float* __restrict__ b2, float* outp)
{
    extern __shared__ char dsm[];
    uint32_t raw = s2u(dsm);
    const uint32_t S = (raw + 1023u) & ~1023u;

    const int tid = threadIdx.x;
    const int lane = tid & 31;
    const int wid = tid >> 5;
    const int wm = wid >> 1;          // 0..3 (32 rows each)
    const int wn = wid & 1;           // 0..1 (64 cols each)
    const int bm = blockIdx.y * 128;
    const int bn = blockIdx.x * 128;
    const int z = blockIdx.z;

    const __half *Ahp, *Alp, *Whp;
    const float* bias;
    if (mode == 0) {
        Ahp = g_xh; Alp = g_xl;
        Whp = g_wh + (size_t)z * DM2;
        bias = (z == 0) ? b0 : (z == 1) ? b1 : b2;
    } else {
        Ahp = g_aoh; Alp = g_aoh;
        Whp = g_wh + 3 * (size_t)DM2;
        bias = b0;
    }
    const bool two_terms = (mode == 0) && (z == 0);

    const int crow = tid >> 2;        // 0..63
    const int ccol = (tid & 3) * 16;
    uint32_t adst[2];
#pragma unroll
    for (int p = 0; p < 2; p++)
        adst[p] = SWZ64((uint32_t)((crow + 64 * p) * 64 + ccol));

    auto issue = [&](int stg, int kt) {
        uint32_t sb = S + (uint32_t)stg * 24576u;
        size_t ga = (size_t)(bm + crow) * D_MODEL + kt + (ccol >> 1);
        size_t gb = (size_t)(bn + crow) * D_MODEL + kt + (ccol >> 1);
#pragma unroll
        for (int p = 0; p < 2; p++) {
            CP16(sb + adst[p],         Ahp + ga + (size_t)(64 * p) * D_MODEL);
            CP16(sb + 16384 + adst[p], Whp + gb + (size_t)(64 * p) * D_MODEL);
        }
        if (two_terms) {
#pragma unroll
            for (int p = 0; p < 2; p++)
                CP16(sb + 8192 + adst[p], Alp + ga + (size_t)(64 * p) * D_MODEL);
        }
        CP_COMMIT();
    };

    // ldmatrix offsets (kh=0); kh=1 = XOR 32 (bit5 pre-swizzle, unaffected by SWZ64)
    uint32_t aoff[2], boff[4];
#pragma unroll
    for (int mf = 0; mf < 2; mf++) {
        int r = wm * 32 + mf * 16 + (lane & 15);
        aoff[mf] = SWZ64((uint32_t)(r * 64 + ((lane >> 4) << 4)));
    }
#pragma unroll
    for (int nf = 0; nf < 4; nf++) {
        int r = wn * 64 + nf * 16 + (lane & 15);
        boff[nf] = 16384u + SWZ64((uint32_t)(r * 64 + ((lane >> 4) << 4)));
    }

    float acc[2][8][4];
#pragma unroll
    for (int mf = 0; mf < 2; mf++)
#pragma unroll
        for (int j = 0; j < 8; j++)
#pragma unroll
            for (int t = 0; t < 4; t++) acc[mf][j][t] = 0.f;

    issue(0, 0);
    issue(1, 32);

    for (int i = 0; i < 32; i++) {
        asm volatile("cp.async.wait_group 1;" ::: "memory");
        __syncthreads();
        const uint32_t sb = S + (uint32_t)(((uint32_t)i) % 3u) * 24576u;
        if (i + 2 < 32) issue((i + 2) % 3, (i + 2) * 32);
        else CP_COMMIT();

#pragma unroll
        for (int kh = 0; kh < 2; kh++) {
            const uint32_t xk = (uint32_t)(kh * 32);
            uint32_t ah[2][4], al[2][4];
#pragma unroll
            for (int mf = 0; mf < 2; mf++)
                LDSM4(ah[mf], sb + (aoff[mf] ^ xk));
            if (two_terms) {
#pragma unroll
                for (int mf = 0; mf < 2; mf++)
                    LDSM4(al[mf], sb + 8192u + (aoff[mf] ^ xk));
            }
#pragma unroll
            for (int nf = 0; nf < 4; nf++) {
                uint32_t bh[4];
                LDSM4(bh, sb + (boff[nf] ^ xk));
#pragma unroll
                for (int mf = 0; mf < 2; mf++)
#pragma unroll
                    for (int s0 = 0; s0 < 2; s0++)
                        MMAH(acc[mf][nf * 2 + s0], ah[mf], bh[s0], bh[s0 + 2]);
                if (two_terms) {
#pragma unroll
                    for (int mf = 0; mf < 2; mf++)
#pragma unroll
                        for (int s0 = 0; s0 < 2; s0++)
                            MMAH(acc[mf][nf * 2 + s0], al[mf], bh[s0], bh[s0 + 2]);
                }
            }
        }
    }

    const int r0 = lane >> 2;
    const int c0 = (lane & 3) << 1;
#pragma unroll
    for (int mf = 0; mf < 2; mf++) {
        const int m_ = bm + wm * 32 + mf * 16 + r0;
#pragma unroll
        for (int j = 0; j < 8; j++) {
            const int n_ = bn + wn * 64 + j * 8 + c0;
            const float bx = bias[n_], by = bias[n_ + 1];
            float v00 = acc[mf][j][0] + bx, v01 = acc[mf][j][1] + by;
            float v10 = acc[mf][j][2] + bx, v11 = acc[mf][j][3] + by;
            if (mode == 0) {
                const int b_ = m_ >> 11, s_ = m_ & (SS - 1);
                size_t idx = ((((size_t)b_ * NH + (n_ >> 6)) * SS) + s_) * DK + (n_ & 63);
                if (z == 0) {
                    uint32_t lo, hi;
                    hi = pack2h(v00 * 0.125f, v01 * 0.125f, lo);
                    *(uint32_t*)(g_qh + idx) = hi;
                    *(uint32_t*)(g_ql + idx) = lo;
                    hi = pack2h(v10 * 0.125f, v11 * 0.125f, lo);
                    *(uint32_t*)(g_qh + idx + 8 * DK) = hi;
                    *(uint32_t*)(g_ql + idx + 8 * DK) = lo;
                } else {
                    __half* dstp = (z == 1) ? g_kh : g_vh;
                    *(uint32_t*)(dstp + idx) = pack2s(v00, v01);
                    *(uint32_t*)(dstp + idx + 8 * DK) = pack2s(v10, v11);
                }
            } else {
                float* p = outp + (size_t)m_ * D_MODEL + n_;
                *(float2*)p = make_float2(v00, v01);
                *(float2*)(p + 8 * D_MODEL) = make_float2(v10, v11);
            }
        }
    }
}

// ---------------------------------------------------------------------------
// fp16 tensor-core banded flash attention, 2-term Q/P splits; O stored fp16.
// smem: Qh@0 Ql@8192 | 2 stages x (Kh 8K + Vh 8K) at 16384.
// ---------------------------------------------------------------------------
__global__ __launch_bounds__(128, 3) void fa_attn()
{
    extern __shared__ char dsm[];
    uint32_t raw = s2u(dsm);
    const uint32_t S = (raw + 1023u) & ~1023u;

    const int tid = threadIdx.x;
    const int lane = tid & 31;
    const int wid = tid >> 5;
    const int q0 = blockIdx.x * 64;
    const int h = blockIdx.y;
    const int b = blockIdx.z;

    const size_t base = (((size_t)b * NH + h) * SS) * DK;
    const __half* qh = g_qh + base;
    const __half* ql = g_ql + base;
    const __half* kh = g_kh + base;
    const __half* vh = g_vh + base;

    int klo = q0 - (BAND - 1); if (klo < 0) klo = 0;
    int khi = q0 + 63 + (BAND - 1); if (khi > SS - 1) khi = SS - 1;
    const int kt_lo = klo >> 6;
    const int nt = (khi >> 6) - kt_lo + 1;

    auto issue_kv = [&](int st, int kb) {
        uint32_t sb = S + 16384u + (uint32_t)st * 16384u;
#pragma unroll
        for (int i = 0; i < 4; i++) {
            int idx = i * 128 + tid;
            int row = idx >> 3;
            int chb = (idx & 7) * 16;
            uint32_t dsw = SWZ128((uint32_t)(row * 128 + chb));
            size_t g = (size_t)(kb + row) * DK + (chb >> 1);
            CP16(sb + dsw,        kh + g);
            CP16(sb + 8192 + dsw, vh + g);
        }
        CP_COMMIT();
    };

#pragma unroll
    for (int i = 0; i < 4; i++) {
        int idx = i * 128 + tid;
        int row = idx >> 3;
        int chb = (idx & 7) * 16;
        uint32_t dsw = SWZ128((uint32_t)(row * 128 + chb));
        size_t g = (size_t)(q0 + row) * DK + (chb >> 1);
        CP16(S + dsw,        qh + g);
        CP16(S + 8192 + dsw, ql + g);
    }
    issue_kv(0, kt_lo * 64);
    if (nt > 1) issue_kv(1, (kt_lo + 1) * 64);

    uint32_t qfh[4][4], qfl[4][4];
    float o[8][4];
#pragma unroll
    for (int j = 0; j < 8; j++)
#pragma unroll
        for (int t = 0; t < 4; t++) o[j][t] = 0.f;
    float m0 = -1e30f, m1 = -1e30f, l0 = 0.f, l1 = 0.f;

    const int wr_lo = q0 + wid * 16;
    const int r0 = wr_lo + (lane >> 2);

    for (int it = 0; it < nt; it++) {
        if (it + 1 < nt) asm volatile("cp.async.wait_group 1;" ::: "memory");
        else             asm volatile("cp.async.wait_group 0;" ::: "memory");
        __syncthreads();

        if (it == 0) {
            const int qr = wid * 16 + (lane & 15);
#pragma unroll
            for (int dc = 0; dc < 4; dc++) {
                uint32_t ad = SWZ128((uint32_t)(qr * 128 + dc * 32 + ((lane >> 4) << 4)));
                LDSM4(qfh[dc], S + ad);
                LDSM4(qfl[dc], S + 8192u + ad);
            }
        }

        const int kb = (kt_lo + it) * 64;
        const bool active = (kb < wr_lo + 15 + BAND) && (kb + 63 > wr_lo - BAND);

        if (active) {
            const uint32_t kbuf = S + 16384u + (uint32_t)(it & 1) * 16384u;
            const uint32_t vbuf = kbuf + 8192u;

            float s[8][4];
#pragma unroll
            for (int j = 0; j < 8; j++)
#pragma unroll
                for (int t = 0; t < 4; t++) s[j][t] = 0.f;

#pragma unroll
            for (int dc = 0; dc < 4; dc++) {
                const uint32_t colb = dc * 32 + ((lane >> 4) << 4);
#pragma unroll
                for (int np = 0; np < 4; np++) {
                    uint32_t ad = SWZ128((uint32_t)((np * 16 + (lane & 15)) * 128 + colb));
                    uint32_t bh4[4];
                    LDSM4(bh4, kbuf + ad);
#pragma unroll
                    for (int s0 = 0; s0 < 2; s0++)
                        MMAH(s[np * 2 + s0], qfh[dc], bh4[s0], bh4[s0 + 2]);
#pragma unroll
                    for (int s0 = 0; s0 < 2; s0++)
                        MMAH(s[np * 2 + s0], qfl[dc], bh4[s0], bh4[s0 + 2]);
                }
            }

            float mt0 = -1e30f, mt1 = -1e30f;
#pragma unroll
            for (int j = 0; j < 8; j++) {
                const int kjb = kb + j * 8 + (lane & 3) * 2;
#pragma unroll
                for (int c = 0; c < 2; c++) {
                    const int dq0 = r0 - (kjb + c);
                    if (dq0 >= BAND || dq0 <= -BAND) s[j][c] = -1e9f;
                    const int dq1 = dq0 + 8;
                    if (dq1 >= BAND || dq1 <= -BAND) s[j][2 + c] = -1e9f;
                    mt0 = fmaxf(mt0, s[j][c]);
                    mt1 = fmaxf(mt1, s[j][2 + c]);
                }
            }
            mt0 = fmaxf(mt0, __shfl_xor_sync(0xffffffffu, mt0, 1));
            mt0 = fmaxf(mt0, __shfl_xor_sync(0xffffffffu, mt0, 2));
            mt1 = fmaxf(mt1, __shfl_xor_sync(0xffffffffu, mt1, 1));
            mt1 = fmaxf(mt1, __shfl_xor_sync(0xffffffffu, mt1, 2));
            const float mn0 = fmaxf(m0, mt0), mn1 = fmaxf(m1, mt1);
            const float a0 = __expf(m0 - mn0), a1 = __expf(m1 - mn1);
            m0 = mn0; m1 = mn1;
            float ls0 = 0.f, ls1 = 0.f;
#pragma unroll
            for (int j = 0; j < 8; j++)
#pragma unroll
                for (int c = 0; c < 2; c++) {
                    float p = __expf(s[j][c] - mn0);
                    s[j][c] = p; ls0 += p;
                    float p2 = __expf(s[j][2 + c] - mn1);
                    s[j][2 + c] = p2; ls1 += p2;
                }
            ls0 += __shfl_xor_sync(0xffffffffu, ls0, 1);
            ls0 += __shfl_xor_sync(0xffffffffu, ls0, 2);
            ls1 += __shfl_xor_sync(0xffffffffu, ls1, 1);
            ls1 += __shfl_xor_sync(0xffffffffu, ls1, 2);
            l0 = l0 * a0 + ls0;
            l1 = l1 * a1 + ls1;
#pragma unroll
            for (int j = 0; j < 8; j++) {
                o[j][0] *= a0; o[j][1] *= a0;
                o[j][2] *= a1; o[j][3] *= a1;
            }

#pragma unroll
            for (int kc = 0; kc < 4; kc++) {
                uint32_t ph[4], pl[4];
                ph[0] = pack2h(s[2 * kc][0],     s[2 * kc][1],     pl[0]);
                ph[1] = pack2h(s[2 * kc][2],     s[2 * kc][3],     pl[1]);
                ph[2] = pack2h(s[2 * kc + 1][0], s[2 * kc + 1][1], pl[2]);
                ph[3] = pack2h(s[2 * kc + 1][2], s[2 * kc + 1][3], pl[3]);
                const uint32_t rowb = (uint32_t)((kc * 16 + (lane & 15)) * 128 + ((lane >> 4) << 4));
#pragma unroll
                for (int dg = 0; dg < 4; dg++) {
                    uint32_t ad = SWZ128(rowb + dg * 32);
                    uint32_t vh4[4];
                    LDSM4T(vh4, vbuf + ad);
                    MMAH(o[2 * dg],     ph, vh4[0], vh4[1]);
                    MMAH(o[2 * dg + 1], ph, vh4[2], vh4[3]);
                    MMAH(o[2 * dg],     pl, vh4[0], vh4[1]);
                    MMAH(o[2 * dg + 1], pl, vh4[2], vh4[3]);
                }
            }
        }

        __syncthreads();
        if (it + 2 < nt) issue_kv(it & 1, (kt_lo + it + 2) * 64);
    }

    // write O as single fp16 (the out-proj reads it single-term)
    const float inv0 = 1.f / l0, inv1 = 1.f / l1;
    const size_t e0 = ((size_t)(b * SS) + r0) * D_MODEL + h * DK + (lane & 3) * 2;
    const size_t e1 = e0 + 8 * D_MODEL;
#pragma unroll
    for (int j = 0; j < 8; j++) {
        *(uint32_t*)(g_aoh + e0 + j * 8) = pack2s(o[j][0] * inv0, o[j][1] * inv0);
        *(uint32_t*)(g_aoh + e1 + j * 8) = pack2s(o[j][2] * inv1, o[j][3] * inv1);
    }
}

// ---------------------------------------------------------------------------

extern "C" void kernel_launch(void* const* d_in, const int* in_sizes, int n_in,
                              void* d_out, int out_size)
{
    const float* x  = (const float*)d_in[0];
    const float* Wq = (const float*)d_in[1];
    const float* bq = (const float*)d_in[2];
    const float* Wk = (const float*)d_in[3];
    const float* bk = (const float*)d_in[4];
    const float* Wv = (const float*)d_in[5];
    const float* bv = (const float*)d_in[6];
    const float* Wo = (const float*)d_in[7];
    const float* bo = (const float*)d_in[8];
    float* out = (float*)d_out;

    const int GSM = 3 * 24576 + 1024;
    const int ASM = 16384 + 2 * 16384 + 1024;
    static bool attr_done = false;
    if (!attr_done) {
        cudaFuncSetAttribute(tc_gemm, cudaFuncAttributeMaxDynamicSharedMemorySize, GSM);
        cudaFuncSetAttribute(fa_attn, cudaFuncAttributeMaxDynamicSharedMemorySize, ASM);
        attr_done = true;
    }

    const int NCVT = NX4 + 4 * NW4;
    cvt_all<<<(NCVT + 255) / 256, 256>>>((const float4*)x, (const float4*)Wq,
                                         (const float4*)Wk, (const float4*)Wv,
                                         (const float4*)Wo);

    tc_gemm<<<dim3(D_MODEL / 128, M_TOT / 128, 3), 256, GSM>>>(0, bq, bk, bv, nullptr);
    fa_attn<<<dim3(SS / 64, NH, BB), 128, ASM>>>();
    tc_gemm<<<dim3(D_MODEL / 128, M_TOT / 128, 1), 256, GSM>>>(1, bo, bo, bo, out);
}

// round 13
// speedup vs baseline: 1.2051x; 1.2051x over previous
#include <cuda_runtime.h>
#include <cuda_fp16.h>
#include <cstdint>
#include <math.h>

#define D_MODEL 1024
#define NH 16
#define DK 64
#define BAND 100
#define BB 2
#define SS 2048
#define M_TOT (BB * SS)
#define DM2 (D_MODEL * D_MODEL)

// ---------------- scratch (device globals; no allocs allowed) ----------------
__device__ __align__(256) __half g_qh[BB * NH * SS * DK];   // Q hi (scaled 0.125)
__device__ __align__(256) __half g_ql[BB * NH * SS * DK];   // Q lo
__device__ __align__(256) __half g_kh[BB * NH * SS * DK];   // K single
__device__ __align__(256) __half g_vh[BB * NH * SS * DK];   // V single
__device__ __align__(256) __half g_xh[M_TOT * D_MODEL];     // x hi
__device__ __align__(256) __half g_xl[M_TOT * D_MODEL];     // x lo
__device__ __align__(256) __half g_wh[4 * DM2];             // W single (4 slots)
__device__ __align__(256) __half g_aoh[M_TOT * D_MODEL];    // attn out (single fp16)

// ---------------- helpers ----------------
__device__ __forceinline__ uint32_t s2u(const void* p) {
    uint32_t a;
    asm("{ .reg .u64 t; cvta.to.shared.u64 t, %1; cvt.u32.u64 %0, t; }" : "=r"(a) : "l"(p));
    return a;
}

#define SWZ128(o) ((o) ^ (((o) >> 3) & 0x70))

#define CP16(dst, src) \
    asm volatile("cp.async.cg.shared.global [%0], [%1], 16;" :: "r"(dst), "l"(src))
#define CP_COMMIT() asm volatile("cp.async.commit_group;" ::: "memory")

#define LDSM4(r, addr) \
    asm volatile("ldmatrix.sync.aligned.m8n8.x4.shared.b16 {%0,%1,%2,%3}, [%4];" \
                 : "=r"((r)[0]), "=r"((r)[1]), "=r"((r)[2]), "=r"((r)[3]) : "r"(addr))
#define LDSM4T(r, addr) \
    asm volatile("ldmatrix.sync.aligned.m8n8.x4.trans.shared.b16 {%0,%1,%2,%3}, [%4];" \
                 : "=r"((r)[0]), "=r"((r)[1]), "=r"((r)[2]), "=r"((r)[3]) : "r"(addr))

#define MMAH(d, a, bx, by) \
    asm volatile("mma.sync.aligned.m16n8k16.row.col.f32.f16.f16.f32 " \
                 "{%0,%1,%2,%3}, {%4,%5,%6,%7}, {%8,%9}, {%0,%1,%2,%3};" \
                 : "+f"((d)[0]), "+f"((d)[1]), "+f"((d)[2]), "+f"((d)[3]) \
                 : "r"((a)[0]), "r"((a)[1]), "r"((a)[2]), "r"((a)[3]), "r"(bx), "r"(by))

__device__ __forceinline__ uint32_t pack2h(float a, float b, uint32_t& lo) {
    __half2 h = __floats2half2_rn(a, b);
    __half2 l = __floats2half2_rn(a - __low2float(h), b - __high2float(h));
    lo = *reinterpret_cast<uint32_t*>(&l);
    return *reinterpret_cast<uint32_t*>(&h);
}
__device__ __forceinline__ uint32_t pack2s(float a, float b) {
    __half2 h = __floats2half2_rn(a, b);
    return *reinterpret_cast<uint32_t*>(&h);
}

// ---------------- fp32 -> fp16 conversions (single launch) ----------------
#define NX4 (M_TOT * D_MODEL / 4)
#define NW4 (DM2 / 4)

__global__ void cvt_all(const float4* __restrict__ x,
                        const float4* __restrict__ wq, const float4* __restrict__ wk,
                        const float4* __restrict__ wv, const float4* __restrict__ wo)
{
    int i = blockIdx.x * blockDim.x + threadIdx.x;
    if (i < NX4) {
        float4 v = x[i];
        uint2 hv, lv;
        hv.x = pack2h(v.x, v.y, lv.x);
        hv.y = pack2h(v.z, v.w, lv.y);
        ((uint2*)g_xh)[i] = hv;
        ((uint2*)g_xl)[i] = lv;
    } else {
        int j = i - NX4;
        if (j >= 4 * NW4) return;
        int slot = j >> 18;
        int k = j & (NW4 - 1);
        const float4* src = (slot == 0) ? wq : (slot == 1) ? wk : (slot == 2) ? wv : wo;
        float4 v = src[k];
        uint2 hv;
        hv.x = pack2s(v.x, v.y);
        hv.y = pack2s(v.z, v.w);
        ((uint2*)g_wh)[j] = hv;
    }
}

// ---------------------------------------------------------------------------
// HMMA fp16 GEMM. CTA 128x128, 4 warps (2x2, warp 64x64), K-chunk 64,
// 2-stage cp.async double buffer (48KB/stage), 128 threads, 2 CTAs/SM.
// two_terms (Q proj only): D = (Ah+Al) @ W^T; else D = Ah @ W^T.
// stage (48KB, 128B rows, SW128): Ah@0  Al@16384  Bh@32768
// ---------------------------------------------------------------------------
__global__ __launch_bounds__(128, 2) void tc_gemm(
    int mode, const float* __restrict__ b0, const float* __restrict__ b1,
    const float* __restrict__ b2, float* outp)
{
    extern __shared__ char dsm[];
    uint32_t raw = s2u(dsm);
    const uint32_t S = (raw + 1023u) & ~1023u;

    const int tid = threadIdx.x;
    const int lane = tid & 31;
    const int wid = tid >> 5;
    const int wm = wid >> 1;          // 0..1 (64 rows)
    const int wn = wid & 1;           // 0..1 (64 cols)
    const int bm = blockIdx.y * 128;
    const int bn = blockIdx.x * 128;
    const int z = blockIdx.z;

    const __half *Ahp, *Alp, *Whp;
    const float* bias;
    if (mode == 0) {
        Ahp = g_xh; Alp = g_xl;
        Whp = g_wh + (size_t)z * DM2;
        bias = (z == 0) ? b0 : (z == 1) ? b1 : b2;
    } else {
        Ahp = g_aoh; Alp = g_aoh;
        Whp = g_wh + 3 * (size_t)DM2;
        bias = b0;
    }
    const bool two_terms = (mode == 0) && (z == 0);

    // cp.async: each thread owns one 128-row, 8 x 16B chunks per tensor
    uint32_t adst[8];
#pragma unroll
    for (int c = 0; c < 8; c++)
        adst[c] = SWZ128((uint32_t)(tid * 128 + c * 16));

    auto issue = [&](int stg, int kt) {
        uint32_t sb = S + (uint32_t)stg * 49152u;
        size_t ga = (size_t)(bm + tid) * D_MODEL + kt;
        size_t gb = (size_t)(bn + tid) * D_MODEL + kt;
#pragma unroll
        for (int c = 0; c < 8; c++) {
            CP16(sb + adst[c],          Ahp + ga + c * 8);
            CP16(sb + 32768 + adst[c],  Whp + gb + c * 8);
        }
        if (two_terms) {
#pragma unroll
            for (int c = 0; c < 8; c++)
                CP16(sb + 16384 + adst[c], Alp + ga + c * 8);
        }
        CP_COMMIT();
    };

    // ldmatrix base offsets (kh=0); kh steps = XOR (kh*32): bits 5-6, disjoint
    // from the lane bit-4 column offset and below SW128's row bits.
    uint32_t aoff[4], boff[4];
#pragma unroll
    for (int mf = 0; mf < 4; mf++) {
        int r = wm * 64 + mf * 16 + (lane & 15);
        aoff[mf] = SWZ128((uint32_t)(r * 128 + ((lane >> 4) << 4)));
    }
#pragma unroll
    for (int nf = 0; nf < 4; nf++) {
        int r = wn * 64 + nf * 16 + (lane & 15);
        boff[nf] = 32768u + SWZ128((uint32_t)(r * 128 + ((lane >> 4) << 4)));
    }

    float acc[4][8][4];
#pragma unroll
    for (int mf = 0; mf < 4; mf++)
#pragma unroll
        for (int j = 0; j < 8; j++)
#pragma unroll
            for (int t = 0; t < 4; t++) acc[mf][j][t] = 0.f;

    issue(0, 0);

    for (int i = 0; i < 16; i++) {
        asm volatile("cp.async.wait_group 0;" ::: "memory");
        __syncthreads();
        // prefetch next stage (overlaps with compute below); the sync above
        // guarantees every warp is done computing on that buffer
        if (i + 1 < 16) issue((i + 1) & 1, (i + 1) * 64);
        const uint32_t sb = S + (uint32_t)(i & 1) * 49152u;

#pragma unroll
        for (int kh = 0; kh < 4; kh++) {
            const uint32_t xk = (uint32_t)(kh * 32);
            uint32_t ah[4][4], al[4][4];
#pragma unroll
            for (int mf = 0; mf < 4; mf++)
                LDSM4(ah[mf], sb + (aoff[mf] ^ xk));
            if (two_terms) {
#pragma unroll
                for (int mf = 0; mf < 4; mf++)
                    LDSM4(al[mf], sb + 16384u + (aoff[mf] ^ xk));
            }
#pragma unroll
            for (int nf = 0; nf < 4; nf++) {
                uint32_t bh[4];
                LDSM4(bh, sb + (boff[nf] ^ xk));
#pragma unroll
                for (int mf = 0; mf < 4; mf++)
#pragma unroll
                    for (int s0 = 0; s0 < 2; s0++)
                        MMAH(acc[mf][nf * 2 + s0], ah[mf], bh[s0], bh[s0 + 2]);
                if (two_terms) {
#pragma unroll
                    for (int mf = 0; mf < 4; mf++)
#pragma unroll
                        for (int s0 = 0; s0 < 2; s0++)
                            MMAH(acc[mf][nf * 2 + s0], al[mf], bh[s0], bh[s0 + 2]);
                }
            }
        }
        __syncthreads();
    }

    const int r0 = lane >> 2;
    const int c0 = (lane & 3) << 1;
#pragma unroll
    for (int mf = 0; mf < 4; mf++) {
        const int m_ = bm + wm * 64 + mf * 16 + r0;
#pragma unroll
        for (int j = 0; j < 8; j++) {
            const int n_ = bn + wn * 64 + j * 8 + c0;
            const float bx = bias[n_], by = bias[n_ + 1];
            float v00 = acc[mf][j][0] + bx, v01 = acc[mf][j][1] + by;
            float v10 = acc[mf][j][2] + bx, v11 = acc[mf][j][3] + by;
            if (mode == 0) {
                const int b_ = m_ >> 11, s_ = m_ & (SS - 1);
                size_t idx = ((((size_t)b_ * NH + (n_ >> 6)) * SS) + s_) * DK + (n_ & 63);
                if (z == 0) {
                    uint32_t lo, hi;
                    hi = pack2h(v00 * 0.125f, v01 * 0.125f, lo);
                    *(uint32_t*)(g_qh + idx) = hi;
                    *(uint32_t*)(g_ql + idx) = lo;
                    hi = pack2h(v10 * 0.125f, v11 * 0.125f, lo);
                    *(uint32_t*)(g_qh + idx + 8 * DK) = hi;
                    *(uint32_t*)(g_ql + idx + 8 * DK) = lo;
                } else {
                    __half* dstp = (z == 1) ? g_kh : g_vh;
                    *(uint32_t*)(dstp + idx) = pack2s(v00, v01);
                    *(uint32_t*)(dstp + idx + 8 * DK) = pack2s(v10, v11);
                }
            } else {
                float* p = outp + (size_t)m_ * D_MODEL + n_;
                *(float2*)p = make_float2(v00, v01);
                *(float2*)(p + 8 * D_MODEL) = make_float2(v10, v11);
            }
        }
    }
}

// ---------------------------------------------------------------------------
// fp16 tensor-core banded flash attention, 2-term Q/P splits; O stored fp16.
// smem: Qh@0 Ql@8192 | 2 stages x (Kh 8K + Vh 8K) at 16384.  (unchanged R11)
// ---------------------------------------------------------------------------
__global__ __launch_bounds__(128, 3) void fa_attn()
{
    extern __shared__ char dsm[];
    uint32_t raw = s2u(dsm);
    const uint32_t S = (raw + 1023u) & ~1023u;

    const int tid = threadIdx.x;
    const int lane = tid & 31;
    const int wid = tid >> 5;
    const int q0 = blockIdx.x * 64;
    const int h = blockIdx.y;
    const int b = blockIdx.z;

    const size_t base = (((size_t)b * NH + h) * SS) * DK;
    const __half* qh = g_qh + base;
    const __half* ql = g_ql + base;
    const __half* kh = g_kh + base;
    const __half* vh = g_vh + base;

    int klo = q0 - (BAND - 1); if (klo < 0) klo = 0;
    int khi = q0 + 63 + (BAND - 1); if (khi > SS - 1) khi = SS - 1;
    const int kt_lo = klo >> 6;
    const int nt = (khi >> 6) - kt_lo + 1;

    auto issue_kv = [&](int st, int kb) {
        uint32_t sb = S + 16384u + (uint32_t)st * 16384u;
#pragma unroll
        for (int i = 0; i < 4; i++) {
            int idx = i * 128 + tid;
            int row = idx >> 3;
            int chb = (idx & 7) * 16;
            uint32_t dsw = SWZ128((uint32_t)(row * 128 + chb));
            size_t g = (size_t)(kb + row) * DK + (chb >> 1);
            CP16(sb + dsw,        kh + g);
            CP16(sb + 8192 + dsw, vh + g);
        }
        CP_COMMIT();
    };

#pragma unroll
    for (int i = 0; i < 4; i++) {
        int idx = i * 128 + tid;
        int row = idx >> 3;
        int chb = (idx & 7) * 16;
        uint32_t dsw = SWZ128((uint32_t)(row * 128 + chb));
        size_t g = (size_t)(q0 + row) * DK + (chb >> 1);
        CP16(S + dsw,        qh + g);
        CP16(S + 8192 + dsw, ql + g);
    }
    issue_kv(0, kt_lo * 64);
    if (nt > 1) issue_kv(1, (kt_lo + 1) * 64);

    uint32_t qfh[4][4], qfl[4][4];
    float o[8][4];
#pragma unroll
    for (int j = 0; j < 8; j++)
#pragma unroll
        for (int t = 0; t < 4; t++) o[j][t] = 0.f;
    float m0 = -1e30f, m1 = -1e30f, l0 = 0.f, l1 = 0.f;

    const int wr_lo = q0 + wid * 16;
    const int r0 = wr_lo + (lane >> 2);

    for (int it = 0; it < nt; it++) {
        if (it + 1 < nt) asm volatile("cp.async.wait_group 1;" ::: "memory");
        else             asm volatile("cp.async.wait_group 0;" ::: "memory");
        __syncthreads();

        if (it == 0) {
            const int qr = wid * 16 + (lane & 15);
#pragma unroll
            for (int dc = 0; dc < 4; dc++) {
                uint32_t ad = SWZ128((uint32_t)(qr * 128 + dc * 32 + ((lane >> 4) << 4)));
                LDSM4(qfh[dc], S + ad);
                LDSM4(qfl[dc], S + 8192u + ad);
            }
        }

        const int kb = (kt_lo + it) * 64;
        const bool active = (kb < wr_lo + 15 + BAND) && (kb + 63 > wr_lo - BAND);

        if (active) {
            const uint32_t kbuf = S + 16384u + (uint32_t)(it & 1) * 16384u;
            const uint32_t vbuf = kbuf + 8192u;

            float s[8][4];
#pragma unroll
            for (int j = 0; j < 8; j++)
#pragma unroll
                for (int t = 0; t < 4; t++) s[j][t] = 0.f;

#pragma unroll
            for (int dc = 0; dc < 4; dc++) {
                const uint32_t colb = dc * 32 + ((lane >> 4) << 4);
#pragma unroll
                for (int np = 0; np < 4; np++) {
                    uint32_t ad = SWZ128((uint32_t)((np * 16 + (lane & 15)) * 128 + colb));
                    uint32_t bh4[4];
                    LDSM4(bh4, kbuf + ad);
#pragma unroll
                    for (int s0 = 0; s0 < 2; s0++)
                        MMAH(s[np * 2 + s0], qfh[dc], bh4[s0], bh4[s0 + 2]);
#pragma unroll
                    for (int s0 = 0; s0 < 2; s0++)
                        MMAH(s[np * 2 + s0], qfl[dc], bh4[s0], bh4[s0 + 2]);
                }
            }

            float mt0 = -1e30f, mt1 = -1e30f;
#pragma unroll
            for (int j = 0; j < 8; j++) {
                const int kjb = kb + j * 8 + (lane & 3) * 2;
#pragma unroll
                for (int c = 0; c < 2; c++) {
                    const int dq0 = r0 - (kjb + c);
                    if (dq0 >= BAND || dq0 <= -BAND) s[j][c] = -1e9f;
                    const int dq1 = dq0 + 8;
                    if (dq1 >= BAND || dq1 <= -BAND) s[j][2 + c] = -1e9f;
                    mt0 = fmaxf(mt0, s[j][c]);
                    mt1 = fmaxf(mt1, s[j][2 + c]);
                }
            }
            mt0 = fmaxf(mt0, __shfl_xor_sync(0xffffffffu, mt0, 1));
            mt0 = fmaxf(mt0, __shfl_xor_sync(0xffffffffu, mt0, 2));
            mt1 = fmaxf(mt1, __shfl_xor_sync(0xffffffffu, mt1, 1));
            mt1 = fmaxf(mt1, __shfl_xor_sync(0xffffffffu, mt1, 2));
            const float mn0 = fmaxf(m0, mt0), mn1 = fmaxf(m1, mt1);
            const float a0 = __expf(m0 - mn0), a1 = __expf(m1 - mn1);
            m0 = mn0; m1 = mn1;
            float ls0 = 0.f, ls1 = 0.f;
#pragma unroll
            for (int j = 0; j < 8; j++)
#pragma unroll
                for (int c = 0; c < 2; c++) {
                    float p = __expf(s[j][c] - mn0);
                    s[j][c] = p; ls0 += p;
                    float p2 = __expf(s[j][2 + c] - mn1);
                    s[j][2 + c] = p2; ls1 += p2;
                }
            ls0 += __shfl_xor_sync(0xffffffffu, ls0, 1);
            ls0 += __shfl_xor_sync(0xffffffffu, ls0, 2);
            ls1 += __shfl_xor_sync(0xffffffffu, ls1, 1);
            ls1 += __shfl_xor_sync(0xffffffffu, ls1, 2);
            l0 = l0 * a0 + ls0;
            l1 = l1 * a1 + ls1;
#pragma unroll
            for (int j = 0; j < 8; j++) {
                o[j][0] *= a0; o[j][1] *= a0;
                o[j][2] *= a1; o[j][3] *= a1;
            }

#pragma unroll
            for (int kc = 0; kc < 4; kc++) {
                uint32_t ph[4], pl[4];
                ph[0] = pack2h(s[2 * kc][0],     s[2 * kc][1],     pl[0]);
                ph[1] = pack2h(s[2 * kc][2],     s[2 * kc][3],     pl[1]);
                ph[2] = pack2h(s[2 * kc + 1][0], s[2 * kc + 1][1], pl[2]);
                ph[3] = pack2h(s[2 * kc + 1][2], s[2 * kc + 1][3], pl[3]);
                const uint32_t rowb = (uint32_t)((kc * 16 + (lane & 15)) * 128 + ((lane >> 4) << 4));
#pragma unroll
                for (int dg = 0; dg < 4; dg++) {
                    uint32_t ad = SWZ128(rowb + dg * 32);
                    uint32_t vh4[4];
                    LDSM4T(vh4, vbuf + ad);
                    MMAH(o[2 * dg],     ph, vh4[0], vh4[1]);
                    MMAH(o[2 * dg + 1], ph, vh4[2], vh4[3]);
                    MMAH(o[2 * dg],     pl, vh4[0], vh4[1]);
                    MMAH(o[2 * dg + 1], pl, vh4[2], vh4[3]);
                }
            }
        }

        __syncthreads();
        if (it + 2 < nt) issue_kv(it & 1, (kt_lo + it + 2) * 64);
    }

    const float inv0 = 1.f / l0, inv1 = 1.f / l1;
    const size_t e0 = ((size_t)(b * SS) + r0) * D_MODEL + h * DK + (lane & 3) * 2;
    const size_t e1 = e0 + 8 * D_MODEL;
#pragma unroll
    for (int j = 0; j < 8; j++) {
        *(uint32_t*)(g_aoh + e0 + j * 8) = pack2s(o[j][0] * inv0, o[j][1] * inv0);
        *(uint32_t*)(g_aoh + e1 + j * 8) = pack2s(o[j][2] * inv1, o[j][3] * inv1);
    }
}

// ---------------------------------------------------------------------------

extern "C" void kernel_launch(void* const* d_in, const int* in_sizes, int n_in,
                              void* d_out, int out_size)
{
    const float* x  = (const float*)d_in[0];
    const float* Wq = (const float*)d_in[1];
    const float* bq = (const float*)d_in[2];
    const float* Wk = (const float*)d_in[3];
    const float* bk = (const float*)d_in[4];
    const float* Wv = (const float*)d_in[5];
    const float* bv = (const float*)d_in[6];
    const float* Wo = (const float*)d_in[7];
    const float* bo = (const float*)d_in[8];
    float* out = (float*)d_out;

    const int GSM = 2 * 49152 + 1024;           // 99328 B/CTA -> 2 CTAs/SM
    const int ASM = 16384 + 2 * 16384 + 1024;   // 50176 B/CTA
    static bool attr_done = false;
    if (!attr_done) {
        cudaFuncSetAttribute(tc_gemm, cudaFuncAttributeMaxDynamicSharedMemorySize, GSM);
        cudaFuncSetAttribute(fa_attn, cudaFuncAttributeMaxDynamicSharedMemorySize, ASM);
        attr_done = true;
    }

    const int NCVT = NX4 + 4 * NW4;
    cvt_all<<<(NCVT + 255) / 256, 256>>>((const float4*)x, (const float4*)Wq,
                                         (const float4*)Wk, (const float4*)Wv,
                                         (const float4*)Wo);

    tc_gemm<<<dim3(D_MODEL / 128, M_TOT / 128, 3), 128, GSM>>>(0, bq, bk, bv, nullptr);
    fa_attn<<<dim3(SS / 64, NH, BB), 128, ASM>>>();
    tc_gemm<<<dim3(D_MODEL / 128, M_TOT / 128, 1), 128, GSM>>>(1, bo, bo, bo, out);
}

// round 14
// speedup vs baseline: 1.6314x; 1.3537x over previous
#include <cuda_runtime.h>
#include <cuda_fp16.h>
#include <cstdint>
#include <math.h>

#define D_MODEL 1024
#define NH 16
#define DK 64
#define BAND 100
#define BB 2
#define SS 2048
#define M_TOT (BB * SS)
#define DM2 (D_MODEL * D_MODEL)

// ---------------- scratch (device globals; no allocs allowed) ----------------
__device__ __align__(256) __half g_qh[BB * NH * SS * DK];   // Q hi (scaled 0.125)
__device__ __align__(256) __half g_ql[BB * NH * SS * DK];   // Q lo
__device__ __align__(256) __half g_kh[BB * NH * SS * DK];   // K single
__device__ __align__(256) __half g_vh[BB * NH * SS * DK];   // V single
__device__ __align__(256) __half g_xh[M_TOT * D_MODEL];     // x hi
__device__ __align__(256) __half g_xl[M_TOT * D_MODEL];     // x lo
__device__ __align__(256) __half g_wh[4 * DM2];             // W single (4 slots)
__device__ __align__(256) __half g_aoh[M_TOT * D_MODEL];    // attn out (single fp16)

// ---------------- helpers ----------------
__device__ __forceinline__ uint32_t s2u(const void* p) {
    uint32_t a;
    asm("{ .reg .u64 t; cvta.to.shared.u64 t, %1; cvt.u32.u64 %0, t; }" : "=r"(a) : "l"(p));
    return a;
}

#define SWZ64(o)  ((o) ^ (((o) >> 3) & 0x30))
#define SWZ128(o) ((o) ^ (((o) >> 3) & 0x70))

#define CP16(dst, src) \
    asm volatile("cp.async.cg.shared.global [%0], [%1], 16;" :: "r"(dst), "l"(src))
#define CP_COMMIT() asm volatile("cp.async.commit_group;" ::: "memory")

#define LDSM4(r, addr) \
    asm volatile("ldmatrix.sync.aligned.m8n8.x4.shared.b16 {%0,%1,%2,%3}, [%4];" \
                 : "=r"((r)[0]), "=r"((r)[1]), "=r"((r)[2]), "=r"((r)[3]) : "r"(addr))
#define LDSM4T(r, addr) \
    asm volatile("ldmatrix.sync.aligned.m8n8.x4.trans.shared.b16 {%0,%1,%2,%3}, [%4];" \
                 : "=r"((r)[0]), "=r"((r)[1]), "=r"((r)[2]), "=r"((r)[3]) : "r"(addr))

#define MMAH(d, a, bx, by) \
    asm volatile("mma.sync.aligned.m16n8k16.row.col.f32.f16.f16.f32 " \
                 "{%0,%1,%2,%3}, {%4,%5,%6,%7}, {%8,%9}, {%0,%1,%2,%3};" \
                 : "+f"((d)[0]), "+f"((d)[1]), "+f"((d)[2]), "+f"((d)[3]) \
                 : "r"((a)[0]), "r"((a)[1]), "r"((a)[2]), "r"((a)[3]), "r"(bx), "r"(by))

__device__ __forceinline__ uint32_t pack2h(float a, float b, uint32_t& lo) {
    __half2 h = __floats2half2_rn(a, b);
    __half2 l = __floats2half2_rn(a - __low2float(h), b - __high2float(h));
    lo = *reinterpret_cast<uint32_t*>(&l);
    return *reinterpret_cast<uint32_t*>(&h);
}
__device__ __forceinline__ uint32_t pack2s(float a, float b) {
    __half2 h = __floats2half2_rn(a, b);
    return *reinterpret_cast<uint32_t*>(&h);
}

// ---------------- fp32 -> fp16 conversions (single launch) ----------------
#define NX4 (M_TOT * D_MODEL / 4)
#define NW4 (DM2 / 4)

__global__ void cvt_all(const float4* __restrict__ x,
                        const float4* __restrict__ wq, const float4* __restrict__ wk,
                        const float4* __restrict__ wv, const float4* __restrict__ wo)
{
    int i = blockIdx.x * blockDim.x + threadIdx.x;
    if (i < NX4) {
        float4 v = x[i];
        uint2 hv, lv;
        hv.x = pack2h(v.x, v.y, lv.x);
        hv.y = pack2h(v.z, v.w, lv.y);
        ((uint2*)g_xh)[i] = hv;
        ((uint2*)g_xl)[i] = lv;
    } else {
        int j = i - NX4;
        if (j >= 4 * NW4) return;
        int slot = j >> 18;
        int k = j & (NW4 - 1);
        const float4* src = (slot == 0) ? wq : (slot == 1) ? wk : (slot == 2) ? wv : wo;
        float4 v = src[k];
        uint2 hv;
        hv.x = pack2s(v.x, v.y);
        hv.y = pack2s(v.z, v.w);
        ((uint2*)g_wh)[j] = hv;
    }
}

// ---------------------------------------------------------------------------
// HMMA fp16 GEMM (R11 shape). CTA 128x128, 4 warps (2x2, warp 64x64),
// K-chunk 32, cp.async 4-stage (wait_group 2), 128 threads, 2 CTAs/SM.
// two_terms (Q proj only): D = (Ah+Al) @ W^T; else D = Ah @ W^T.
// stage (24KB): Ah[128x64B]@0  Al@8192  Bh[128x64B]@16384
// ---------------------------------------------------------------------------
__global__ __launch_bounds__(128, 2) void tc_gemm(
    int mode, const float* __restrict__ b0, const float* __restrict__ b1,
    const float* __restrict__ b2, float* outp)
{
    extern __shared__ char dsm[];
    uint32_t raw = s2u(dsm);
    const uint32_t S = (raw + 1023u) & ~1023u;

    const int tid = threadIdx.x;
    const int lane = tid & 31;
    const int wid = tid >> 5;
    const int wm = wid >> 1;
    const int wn = wid & 1;
    const int bm = blockIdx.y * 128;
    const int bn = blockIdx.x * 128;
    const int z = blockIdx.z;

    const __half *Ahp, *Alp, *Whp;
    const float* bias;
    if (mode == 0) {
        Ahp = g_xh; Alp = g_xl;
        Whp = g_wh + (size_t)z * DM2;
        bias = (z == 0) ? b0 : (z == 1) ? b1 : b2;
    } else {
        Ahp = g_aoh; Alp = g_aoh;
        Whp = g_wh + 3 * (size_t)DM2;
        bias = b0;
    }
    const bool two_terms = (mode == 0) && (z == 0);

    const int crow = tid >> 2;        // 0..31
    const int ccol = (tid & 3) * 16;
    uint32_t adst[4];
#pragma unroll
    for (int p = 0; p < 4; p++)
        adst[p] = SWZ64((uint32_t)((crow + 32 * p) * 64 + ccol));

    auto issue = [&](int stg, int kt) {
        uint32_t sb = S + (uint32_t)stg * 24576u;
        size_t ga = (size_t)(bm + crow) * D_MODEL + kt + (ccol >> 1);
        size_t gb = (size_t)(bn + crow) * D_MODEL + kt + (ccol >> 1);
#pragma unroll
        for (int p = 0; p < 4; p++) {
            CP16(sb + adst[p],         Ahp + ga + (size_t)(32 * p) * D_MODEL);
            CP16(sb + 16384 + adst[p], Whp + gb + (size_t)(32 * p) * D_MODEL);
        }
        if (two_terms) {
#pragma unroll
            for (int p = 0; p < 4; p++)
                CP16(sb + 8192 + adst[p], Alp + ga + (size_t)(32 * p) * D_MODEL);
        }
        CP_COMMIT();
    };

    // ldmatrix offsets (kh=0); kh=1 = XOR 32 (bit5 pre-swizzle, unaffected by SWZ64)
    uint32_t aoff[4], boff[4];
#pragma unroll
    for (int mf = 0; mf < 4; mf++) {
        int r = wm * 64 + mf * 16 + (lane & 15);
        aoff[mf] = SWZ64((uint32_t)(r * 64 + ((lane >> 4) << 4)));
    }
#pragma unroll
    for (int nf = 0; nf < 4; nf++) {
        int r = wn * 64 + nf * 16 + (lane & 15);
        boff[nf] = 16384u + SWZ64((uint32_t)(r * 64 + ((lane >> 4) << 4)));
    }

    float acc[4][8][4];
#pragma unroll
    for (int mf = 0; mf < 4; mf++)
#pragma unroll
        for (int j = 0; j < 8; j++)
#pragma unroll
            for (int t = 0; t < 4; t++) acc[mf][j][t] = 0.f;

    issue(0, 0);
    issue(1, 32);
    issue(2, 64);

    for (int i = 0; i < 32; i++) {
        asm volatile("cp.async.wait_group 2;" ::: "memory");
        __syncthreads();
        const uint32_t sb = S + (uint32_t)(((uint32_t)i) & 3u) * 24576u;
        // stage (i+3)&3 == (i-1)&3: its compute finished last iteration and the
        // sync above closes it for all warps.
        if (i + 3 < 32) issue((i + 3) & 3, (i + 3) * 32);
        else CP_COMMIT();

#pragma unroll
        for (int kh = 0; kh < 2; kh++) {
            const uint32_t xk = (uint32_t)(kh * 32);
            uint32_t ah[4][4], al[4][4];
#pragma unroll
            for (int mf = 0; mf < 4; mf++)
                LDSM4(ah[mf], sb + (aoff[mf] ^ xk));
            if (two_terms) {
#pragma unroll
                for (int mf = 0; mf < 4; mf++)
                    LDSM4(al[mf], sb + 8192u + (aoff[mf] ^ xk));
            }
#pragma unroll
            for (int nf = 0; nf < 4; nf++) {
                uint32_t bh[4];
                LDSM4(bh, sb + (boff[nf] ^ xk));
#pragma unroll
                for (int mf = 0; mf < 4; mf++)
#pragma unroll
                    for (int s0 = 0; s0 < 2; s0++)
                        MMAH(acc[mf][nf * 2 + s0], ah[mf], bh[s0], bh[s0 + 2]);
                if (two_terms) {
#pragma unroll
                    for (int mf = 0; mf < 4; mf++)
#pragma unroll
                        for (int s0 = 0; s0 < 2; s0++)
                            MMAH(acc[mf][nf * 2 + s0], al[mf], bh[s0], bh[s0 + 2]);
                }
            }
        }
        __syncthreads();
    }

    const int r0 = lane >> 2;
    const int c0 = (lane & 3) << 1;
#pragma unroll
    for (int mf = 0; mf < 4; mf++) {
        const int m_ = bm + wm * 64 + mf * 16 + r0;
#pragma unroll
        for (int j = 0; j < 8; j++) {
            const int n_ = bn + wn * 64 + j * 8 + c0;
            const float bx = bias[n_], by = bias[n_ + 1];
            float v00 = acc[mf][j][0] + bx, v01 = acc[mf][j][1] + by;
            float v10 = acc[mf][j][2] + bx, v11 = acc[mf][j][3] + by;
            if (mode == 0) {
                const int b_ = m_ >> 11, s_ = m_ & (SS - 1);
                size_t idx = ((((size_t)b_ * NH + (n_ >> 6)) * SS) + s_) * DK + (n_ & 63);
                if (z == 0) {
                    uint32_t lo, hi;
                    hi = pack2h(v00 * 0.125f, v01 * 0.125f, lo);
                    *(uint32_t*)(g_qh + idx) = hi;
                    *(uint32_t*)(g_ql + idx) = lo;
                    hi = pack2h(v10 * 0.125f, v11 * 0.125f, lo);
                    *(uint32_t*)(g_qh + idx + 8 * DK) = hi;
                    *(uint32_t*)(g_ql + idx + 8 * DK) = lo;
                } else {
                    __half* dstp = (z == 1) ? g_kh : g_vh;
                    *(uint32_t*)(dstp + idx) = pack2s(v00, v01);
                    *(uint32_t*)(dstp + idx + 8 * DK) = pack2s(v10, v11);
                }
            } else {
                float* p = outp + (size_t)m_ * D_MODEL + n_;
                *(float2*)p = make_float2(v00, v01);
                *(float2*)(p + 8 * D_MODEL) = make_float2(v10, v11);
            }
        }
    }
}

// ---------------------------------------------------------------------------
// fp16 tensor-core banded flash attention, 2-term Q/P splits; O stored fp16.
// smem: Qh@0 Ql@8192 | 2 stages x (Kh 8K + Vh 8K) at 16384.  (unchanged R11)
// ---------------------------------------------------------------------------
__global__ __launch_bounds__(128, 3) void fa_attn()
{
    extern __shared__ char dsm[];
    uint32_t raw = s2u(dsm);
    const uint32_t S = (raw + 1023u) & ~1023u;

    const int tid = threadIdx.x;
    const int lane = tid & 31;
    const int wid = tid >> 5;
    const int q0 = blockIdx.x * 64;
    const int h = blockIdx.y;
    const int b = blockIdx.z;

    const size_t base = (((size_t)b * NH + h) * SS) * DK;
    const __half* qh = g_qh + base;
    const __half* ql = g_ql + base;
    const __half* kh = g_kh + base;
    const __half* vh = g_vh + base;

    int klo = q0 - (BAND - 1); if (klo < 0) klo = 0;
    int khi = q0 + 63 + (BAND - 1); if (khi > SS - 1) khi = SS - 1;
    const int kt_lo = klo >> 6;
    const int nt = (khi >> 6) - kt_lo + 1;

    auto issue_kv = [&](int st, int kb) {
        uint32_t sb = S + 16384u + (uint32_t)st * 16384u;
#pragma unroll
        for (int i = 0; i < 4; i++) {
            int idx = i * 128 + tid;
            int row = idx >> 3;
            int chb = (idx & 7) * 16;
            uint32_t dsw = SWZ128((uint32_t)(row * 128 + chb));
            size_t g = (size_t)(kb + row) * DK + (chb >> 1);
            CP16(sb + dsw,        kh + g);
            CP16(sb + 8192 + dsw, vh + g);
        }
        CP_COMMIT();
    };

#pragma unroll
    for (int i = 0; i < 4; i++) {
        int idx = i * 128 + tid;
        int row = idx >> 3;
        int chb = (idx & 7) * 16;
        uint32_t dsw = SWZ128((uint32_t)(row * 128 + chb));
        size_t g = (size_t)(q0 + row) * DK + (chb >> 1);
        CP16(S + dsw,        qh + g);
        CP16(S + 8192 + dsw, ql + g);
    }
    issue_kv(0, kt_lo * 64);
    if (nt > 1) issue_kv(1, (kt_lo + 1) * 64);

    uint32_t qfh[4][4], qfl[4][4];
    float o[8][4];
#pragma unroll
    for (int j = 0; j < 8; j++)
#pragma unroll
        for (int t = 0; t < 4; t++) o[j][t] = 0.f;
    float m0 = -1e30f, m1 = -1e30f, l0 = 0.f, l1 = 0.f;

    const int wr_lo = q0 + wid * 16;
    const int r0 = wr_lo + (lane >> 2);

    for (int it = 0; it < nt; it++) {
        if (it + 1 < nt) asm volatile("cp.async.wait_group 1;" ::: "memory");
        else             asm volatile("cp.async.wait_group 0;" ::: "memory");
        __syncthreads();

        if (it == 0) {
            const int qr = wid * 16 + (lane & 15);
#pragma unroll
            for (int dc = 0; dc < 4; dc++) {
                uint32_t ad = SWZ128((uint32_t)(qr * 128 + dc * 32 + ((lane >> 4) << 4)));
                LDSM4(qfh[dc], S + ad);
                LDSM4(qfl[dc], S + 8192u + ad);
            }
        }

        const int kb = (kt_lo + it) * 64;
        const bool active = (kb < wr_lo + 15 + BAND) && (kb + 63 > wr_lo - BAND);

        if (active) {
            const uint32_t kbuf = S + 16384u + (uint32_t)(it & 1) * 16384u;
            const uint32_t vbuf = kbuf + 8192u;

            float s[8][4];
#pragma unroll
            for (int j = 0; j < 8; j++)
#pragma unroll
                for (int t = 0; t < 4; t++) s[j][t] = 0.f;

#pragma unroll
            for (int dc = 0; dc < 4; dc++) {
                const uint32_t colb = dc * 32 + ((lane >> 4) << 4);
#pragma unroll
                for (int np = 0; np < 4; np++) {
                    uint32_t ad = SWZ128((uint32_t)((np * 16 + (lane & 15)) * 128 + colb));
                    uint32_t bh4[4];
                    LDSM4(bh4, kbuf + ad);
#pragma unroll
                    for (int s0 = 0; s0 < 2; s0++)
                        MMAH(s[np * 2 + s0], qfh[dc], bh4[s0], bh4[s0 + 2]);
#pragma unroll
                    for (int s0 = 0; s0 < 2; s0++)
                        MMAH(s[np * 2 + s0], qfl[dc], bh4[s0], bh4[s0 + 2]);
                }
            }

            float mt0 = -1e30f, mt1 = -1e30f;
#pragma unroll
            for (int j = 0; j < 8; j++) {
                const int kjb = kb + j * 8 + (lane & 3) * 2;
#pragma unroll
                for (int c = 0; c < 2; c++) {
                    const int dq0 = r0 - (kjb + c);
                    if (dq0 >= BAND || dq0 <= -BAND) s[j][c] = -1e9f;
                    const int dq1 = dq0 + 8;
                    if (dq1 >= BAND || dq1 <= -BAND) s[j][2 + c] = -1e9f;
                    mt0 = fmaxf(mt0, s[j][c]);
                    mt1 = fmaxf(mt1, s[j][2 + c]);
                }
            }
            mt0 = fmaxf(mt0, __shfl_xor_sync(0xffffffffu, mt0, 1));
            mt0 = fmaxf(mt0, __shfl_xor_sync(0xffffffffu, mt0, 2));
            mt1 = fmaxf(mt1, __shfl_xor_sync(0xffffffffu, mt1, 1));
            mt1 = fmaxf(mt1, __shfl_xor_sync(0xffffffffu, mt1, 2));
            const float mn0 = fmaxf(m0, mt0), mn1 = fmaxf(m1, mt1);
            const float a0 = __expf(m0 - mn0), a1 = __expf(m1 - mn1);
            m0 = mn0; m1 = mn1;
            float ls0 = 0.f, ls1 = 0.f;
#pragma unroll
            for (int j = 0; j < 8; j++)
#pragma unroll
                for (int c = 0; c < 2; c++) {
                    float p = __expf(s[j][c] - mn0);
                    s[j][c] = p; ls0 += p;
                    float p2 = __expf(s[j][2 + c] - mn1);
                    s[j][2 + c] = p2; ls1 += p2;
                }
            ls0 += __shfl_xor_sync(0xffffffffu, ls0, 1);
            ls0 += __shfl_xor_sync(0xffffffffu, ls0, 2);
            ls1 += __shfl_xor_sync(0xffffffffu, ls1, 1);
            ls1 += __shfl_xor_sync(0xffffffffu, ls1, 2);
            l0 = l0 * a0 + ls0;
            l1 = l1 * a1 + ls1;
#pragma unroll
            for (int j = 0; j < 8; j++) {
                o[j][0] *= a0; o[j][1] *= a0;
                o[j][2] *= a1; o[j][3] *= a1;
            }

#pragma unroll
            for (int kc = 0; kc < 4; kc++) {
                uint32_t ph[4], pl[4];
                ph[0] = pack2h(s[2 * kc][0],     s[2 * kc][1],     pl[0]);
                ph[1] = pack2h(s[2 * kc][2],     s[2 * kc][3],     pl[1]);
                ph[2] = pack2h(s[2 * kc + 1][0], s[2 * kc + 1][1], pl[2]);
                ph[3] = pack2h(s[2 * kc + 1][2], s[2 * kc + 1][3], pl[3]);
                const uint32_t rowb = (uint32_t)((kc * 16 + (lane & 15)) * 128 + ((lane >> 4) << 4));
#pragma unroll
                for (int dg = 0; dg < 4; dg++) {
                    uint32_t ad = SWZ128(rowb + dg * 32);
                    uint32_t vh4[4];
                    LDSM4T(vh4, vbuf + ad);
                    MMAH(o[2 * dg],     ph, vh4[0], vh4[1]);
                    MMAH(o[2 * dg + 1], ph, vh4[2], vh4[3]);
                    MMAH(o[2 * dg],     pl, vh4[0], vh4[1]);
                    MMAH(o[2 * dg + 1], pl, vh4[2], vh4[3]);
                }
            }
        }

        __syncthreads();
        if (it + 2 < nt) issue_kv(it & 1, (kt_lo + it + 2) * 64);
    }

    const float inv0 = 1.f / l0, inv1 = 1.f / l1;
    const size_t e0 = ((size_t)(b * SS) + r0) * D_MODEL + h * DK + (lane & 3) * 2;
    const size_t e1 = e0 + 8 * D_MODEL;
#pragma unroll
    for (int j = 0; j < 8; j++) {
        *(uint32_t*)(g_aoh + e0 + j * 8) = pack2s(o[j][0] * inv0, o[j][1] * inv0);
        *(uint32_t*)(g_aoh + e1 + j * 8) = pack2s(o[j][2] * inv1, o[j][3] * inv1);
    }
}

// ---------------------------------------------------------------------------

extern "C" void kernel_launch(void* const* d_in, const int* in_sizes, int n_in,
                              void* d_out, int out_size)
{
    const float* x  = (const float*)d_in[0];
    const float* Wq = (const float*)d_in[1];
    const float* bq = (const float*)d_in[2];
    const float* Wk = (const float*)d_in[3];
    const float* bk = (const float*)d_in[4];
    const float* Wv = (const float*)d_in[5];
    const float* bv = (const float*)d_in[6];
    const float* Wo = (const float*)d_in[7];
    const float* bo = (const float*)d_in[8];
    float* out = (float*)d_out;

    const int GSM = 4 * 24576 + 1024;           // 99328 B/CTA -> 2 CTAs/SM
    const int ASM = 16384 + 2 * 16384 + 1024;   // 50176 B/CTA
    static bool attr_done = false;
    if (!attr_done) {
        cudaFuncSetAttribute(tc_gemm, cudaFuncAttributeMaxDynamicSharedMemorySize, GSM);
        cudaFuncSetAttribute(fa_attn, cudaFuncAttributeMaxDynamicSharedMemorySize, ASM);
        attr_done = true;
    }

    const int NCVT = NX4 + 4 * NW4;
    cvt_all<<<(NCVT + 255) / 256, 256>>>((const float4*)x, (const float4*)Wq,
                                         (const float4*)Wk, (const float4*)Wv,
                                         (const float4*)Wo);

    tc_gemm<<<dim3(D_MODEL / 128, M_TOT / 128, 3), 128, GSM>>>(0, bq, bk, bv, nullptr);
    fa_attn<<<dim3(SS / 64, NH, BB), 128, ASM>>>();
    tc_gemm<<<dim3(D_MODEL / 128, M_TOT / 128, 1), 128, GSM>>>(1, bo, bo, bo, out);
}

// round 15
// speedup vs baseline: 2.2365x; 1.3709x over previous
#include <cuda_runtime.h>
#include <cuda_fp16.h>
#include <cstdint>
#include <math.h>

#define D_MODEL 1024
#define NH 16
#define DK 64
#define BAND 100
#define BB 2
#define SS 2048
#define M_TOT (BB * SS)
#define DM2 (D_MODEL * D_MODEL)

// ---------------- scratch (device globals; no allocs allowed) ----------------
__device__ __align__(256) __half g_qh[BB * NH * SS * DK];   // Q (scaled 0.125)
__device__ __align__(256) __half g_kh[BB * NH * SS * DK];   // K
__device__ __align__(256) __half g_vh[BB * NH * SS * DK];   // V
__device__ __align__(256) __half g_xh[M_TOT * D_MODEL];     // x fp16
__device__ __align__(256) __half g_wh[4 * DM2];             // W fp16 (4 slots)
__device__ __align__(256) __half g_aoh[M_TOT * D_MODEL];    // attn out fp16

// ---------------- helpers ----------------
__device__ __forceinline__ uint32_t s2u(const void* p) {
    uint32_t a;
    asm("{ .reg .u64 t; cvta.to.shared.u64 t, %1; cvt.u32.u64 %0, t; }" : "=r"(a) : "l"(p));
    return a;
}

#define SWZ64(o)  ((o) ^ (((o) >> 3) & 0x30))
#define SWZ128(o) ((o) ^ (((o) >> 3) & 0x70))

#define CP16(dst, src) \
    asm volatile("cp.async.cg.shared.global [%0], [%1], 16;" :: "r"(dst), "l"(src))
#define CP_COMMIT() asm volatile("cp.async.commit_group;" ::: "memory")

#define LDSM4(r, addr) \
    asm volatile("ldmatrix.sync.aligned.m8n8.x4.shared.b16 {%0,%1,%2,%3}, [%4];" \
                 : "=r"((r)[0]), "=r"((r)[1]), "=r"((r)[2]), "=r"((r)[3]) : "r"(addr))
#define LDSM4T(r, addr) \
    asm volatile("ldmatrix.sync.aligned.m8n8.x4.trans.shared.b16 {%0,%1,%2,%3}, [%4];" \
                 : "=r"((r)[0]), "=r"((r)[1]), "=r"((r)[2]), "=r"((r)[3]) : "r"(addr))

#define MMAH(d, a, bx, by) \
    asm volatile("mma.sync.aligned.m16n8k16.row.col.f32.f16.f16.f32 " \
                 "{%0,%1,%2,%3}, {%4,%5,%6,%7}, {%8,%9}, {%0,%1,%2,%3};" \
                 : "+f"((d)[0]), "+f"((d)[1]), "+f"((d)[2]), "+f"((d)[3]) \
                 : "r"((a)[0]), "r"((a)[1]), "r"((a)[2]), "r"((a)[3]), "r"(bx), "r"(by))

__device__ __forceinline__ uint32_t pack2h(float a, float b, uint32_t& lo) {
    __half2 h = __floats2half2_rn(a, b);
    __half2 l = __floats2half2_rn(a - __low2float(h), b - __high2float(h));
    lo = *reinterpret_cast<uint32_t*>(&l);
    return *reinterpret_cast<uint32_t*>(&h);
}
__device__ __forceinline__ uint32_t pack2s(float a, float b) {
    __half2 h = __floats2half2_rn(a, b);
    return *reinterpret_cast<uint32_t*>(&h);
}

// ---------------- fp32 -> fp16 conversions (single launch) ----------------
#define NX4 (M_TOT * D_MODEL / 4)
#define NW4 (DM2 / 4)

__global__ void cvt_all(const float4* __restrict__ x,
                        const float4* __restrict__ wq, const float4* __restrict__ wk,
                        const float4* __restrict__ wv, const float4* __restrict__ wo)
{
    int i = blockIdx.x * blockDim.x + threadIdx.x;
    if (i < NX4) {
        float4 v = x[i];
        uint2 hv;
        hv.x = pack2s(v.x, v.y);
        hv.y = pack2s(v.z, v.w);
        ((uint2*)g_xh)[i] = hv;
    } else {
        int j = i - NX4;
        if (j >= 4 * NW4) return;
        int slot = j >> 18;
        int k = j & (NW4 - 1);
        const float4* src = (slot == 0) ? wq : (slot == 1) ? wk : (slot == 2) ? wv : wo;
        float4 v = src[k];
        uint2 hv;
        hv.x = pack2s(v.x, v.y);
        hv.y = pack2s(v.z, v.w);
        ((uint2*)g_wh)[j] = hv;
    }
}

// ---------------------------------------------------------------------------
// HMMA fp16 GEMM, all single-term: D = A @ W^T + bias.
// CTA 128x128, 4 warps (2x2, warp 64x64), K-chunk 32, cp.async 4-stage
// (wait_group 2), 128 threads, one __syncthreads per iteration.
// stage (16KB): A[128x64B]@0  B[128x64B]@8192
// ---------------------------------------------------------------------------
__global__ __launch_bounds__(128, 2) void tc_gemm(
    int mode, const float* __restrict__ b0, const float* __restrict__ b1,
    const float* __restrict__ b2, float* outp)
{
    extern __shared__ char dsm[];
    uint32_t raw = s2u(dsm);
    const uint32_t S = (raw + 1023u) & ~1023u;

    const int tid = threadIdx.x;
    const int lane = tid & 31;
    const int wid = tid >> 5;
    const int wm = wid >> 1;
    const int wn = wid & 1;
    const int bm = blockIdx.y * 128;
    const int bn = blockIdx.x * 128;
    const int z = blockIdx.z;

    const __half *Ahp, *Whp;
    const float* bias;
    if (mode == 0) {
        Ahp = g_xh;
        Whp = g_wh + (size_t)z * DM2;
        bias = (z == 0) ? b0 : (z == 1) ? b1 : b2;
    } else {
        Ahp = g_aoh;
        Whp = g_wh + 3 * (size_t)DM2;
        bias = b0;
    }

    const int crow = tid >> 2;        // 0..31
    const int ccol = (tid & 3) * 16;
    uint32_t adst[4];
#pragma unroll
    for (int p = 0; p < 4; p++)
        adst[p] = SWZ64((uint32_t)((crow + 32 * p) * 64 + ccol));

    auto issue = [&](int stg, int kt) {
        uint32_t sb = S + (uint32_t)stg * 16384u;
        size_t ga = (size_t)(bm + crow) * D_MODEL + kt + (ccol >> 1);
        size_t gb = (size_t)(bn + crow) * D_MODEL + kt + (ccol >> 1);
#pragma unroll
        for (int p = 0; p < 4; p++) {
            CP16(sb + adst[p],        Ahp + ga + (size_t)(32 * p) * D_MODEL);
            CP16(sb + 8192 + adst[p], Whp + gb + (size_t)(32 * p) * D_MODEL);
        }
        CP_COMMIT();
    };

    // ldmatrix offsets (kh=0); kh=1 = XOR 32 (bit5 pre-swizzle, unaffected by SWZ64)
    uint32_t aoff[4], boff[4];
#pragma unroll
    for (int mf = 0; mf < 4; mf++) {
        int r = wm * 64 + mf * 16 + (lane & 15);
        aoff[mf] = SWZ64((uint32_t)(r * 64 + ((lane >> 4) << 4)));
    }
#pragma unroll
    for (int nf = 0; nf < 4; nf++) {
        int r = wn * 64 + nf * 16 + (lane & 15);
        boff[nf] = 8192u + SWZ64((uint32_t)(r * 64 + ((lane >> 4) << 4)));
    }

    float acc[4][8][4];
#pragma unroll
    for (int mf = 0; mf < 4; mf++)
#pragma unroll
        for (int j = 0; j < 8; j++)
#pragma unroll
            for (int t = 0; t < 4; t++) acc[mf][j][t] = 0.f;

    issue(0, 0);
    issue(1, 32);
    issue(2, 64);

    for (int i = 0; i < 32; i++) {
        asm volatile("cp.async.wait_group 2;" ::: "memory");
        __syncthreads();
        // This sync also proves every warp finished iteration i-1's compute on
        // buffer (i-1)&3 == (i+3)&3, so issuing into it now is race-free.
        const uint32_t sb = S + (uint32_t)(((uint32_t)i) & 3u) * 16384u;
        if (i + 3 < 32) issue((i + 3) & 3, (i + 3) * 32);
        else CP_COMMIT();

#pragma unroll
        for (int kh = 0; kh < 2; kh++) {
            const uint32_t xk = (uint32_t)(kh * 32);
            uint32_t ah[4][4];
#pragma unroll
            for (int mf = 0; mf < 4; mf++)
                LDSM4(ah[mf], sb + (aoff[mf] ^ xk));
#pragma unroll
            for (int nf = 0; nf < 4; nf++) {
                uint32_t bh[4];
                LDSM4(bh, sb + (boff[nf] ^ xk));
#pragma unroll
                for (int mf = 0; mf < 4; mf++)
#pragma unroll
                    for (int s0 = 0; s0 < 2; s0++)
                        MMAH(acc[mf][nf * 2 + s0], ah[mf], bh[s0], bh[s0 + 2]);
            }
        }
    }

    const int r0 = lane >> 2;
    const int c0 = (lane & 3) << 1;
#pragma unroll
    for (int mf = 0; mf < 4; mf++) {
        const int m_ = bm + wm * 64 + mf * 16 + r0;
#pragma unroll
        for (int j = 0; j < 8; j++) {
            const int n_ = bn + wn * 64 + j * 8 + c0;
            const float bx = bias[n_], by = bias[n_ + 1];
            float v00 = acc[mf][j][0] + bx, v01 = acc[mf][j][1] + by;
            float v10 = acc[mf][j][2] + bx, v11 = acc[mf][j][3] + by;
            if (mode == 0) {
                const int b_ = m_ >> 11, s_ = m_ & (SS - 1);
                size_t idx = ((((size_t)b_ * NH + (n_ >> 6)) * SS) + s_) * DK + (n_ & 63);
                const float sc = (z == 0) ? 0.125f : 1.f;
                __half* dstp = (z == 0) ? g_qh : (z == 1) ? g_kh : g_vh;
                *(uint32_t*)(dstp + idx) = pack2s(v00 * sc, v01 * sc);
                *(uint32_t*)(dstp + idx + 8 * DK) = pack2s(v10 * sc, v11 * sc);
            } else {
                float* p = outp + (size_t)m_ * D_MODEL + n_;
                *(float2*)p = make_float2(v00, v01);
                *(float2*)(p + 8 * D_MODEL) = make_float2(v10, v11);
            }
        }
    }
}

// ---------------------------------------------------------------------------
// fp16 tensor-core banded flash attention. Q single-term; P hi/lo split in PV.
// smem: Q@0 (8KB) | 2 stages x (K 8K + V 8K) at 8192.
// ---------------------------------------------------------------------------
__global__ __launch_bounds__(128, 3) void fa_attn()
{
    extern __shared__ char dsm[];
    uint32_t raw = s2u(dsm);
    const uint32_t S = (raw + 1023u) & ~1023u;

    const int tid = threadIdx.x;
    const int lane = tid & 31;
    const int wid = tid >> 5;
    const int q0 = blockIdx.x * 64;
    const int h = blockIdx.y;
    const int b = blockIdx.z;

    const size_t base = (((size_t)b * NH + h) * SS) * DK;
    const __half* qh = g_qh + base;
    const __half* kh = g_kh + base;
    const __half* vh = g_vh + base;

    int klo = q0 - (BAND - 1); if (klo < 0) klo = 0;
    int khi = q0 + 63 + (BAND - 1); if (khi > SS - 1) khi = SS - 1;
    const int kt_lo = klo >> 6;
    const int nt = (khi >> 6) - kt_lo + 1;

    auto issue_kv = [&](int st, int kb) {
        uint32_t sb = S + 8192u + (uint32_t)st * 16384u;
#pragma unroll
        for (int i = 0; i < 4; i++) {
            int idx = i * 128 + tid;
            int row = idx >> 3;
            int chb = (idx & 7) * 16;
            uint32_t dsw = SWZ128((uint32_t)(row * 128 + chb));
            size_t g = (size_t)(kb + row) * DK + (chb >> 1);
            CP16(sb + dsw,        kh + g);
            CP16(sb + 8192 + dsw, vh + g);
        }
        CP_COMMIT();
    };

    // group 0: Q tile + KV stage 0
#pragma unroll
    for (int i = 0; i < 4; i++) {
        int idx = i * 128 + tid;
        int row = idx >> 3;
        int chb = (idx & 7) * 16;
        uint32_t dsw = SWZ128((uint32_t)(row * 128 + chb));
        size_t g = (size_t)(q0 + row) * DK + (chb >> 1);
        if (i < 2) {  // Q tile is 8KB: 512 16B-chunks over 128 threads = 4 each
            CP16(S + dsw, qh + g);
        }
    }
    // remaining 2 Q chunks per thread
#pragma unroll
    for (int i = 2; i < 4; i++) {
        int idx = i * 128 + tid;
        int row = idx >> 3;
        int chb = (idx & 7) * 16;
        uint32_t dsw = SWZ128((uint32_t)(row * 128 + chb));
        size_t g = (size_t)(q0 + row) * DK + (chb >> 1);
        CP16(S + dsw, qh + g);
    }
    issue_kv(0, kt_lo * 64);
    if (nt > 1) issue_kv(1, (kt_lo + 1) * 64);

    uint32_t qfh[4][4];
    float o[8][4];
#pragma unroll
    for (int j = 0; j < 8; j++)
#pragma unroll
        for (int t = 0; t < 4; t++) o[j][t] = 0.f;
    float m0 = -1e30f, m1 = -1e30f, l0 = 0.f, l1 = 0.f;

    const int wr_lo = q0 + wid * 16;
    const int r0 = wr_lo + (lane >> 2);

    for (int it = 0; it < nt; it++) {
        if (it + 1 < nt) asm volatile("cp.async.wait_group 1;" ::: "memory");
        else             asm volatile("cp.async.wait_group 0;" ::: "memory");
        __syncthreads();

        if (it == 0) {
            const int qr = wid * 16 + (lane & 15);
#pragma unroll
            for (int dc = 0; dc < 4; dc++) {
                uint32_t ad = SWZ128((uint32_t)(qr * 128 + dc * 32 + ((lane >> 4) << 4)));
                LDSM4(qfh[dc], S + ad);
            }
        }

        const int kb = (kt_lo + it) * 64;
        const bool active = (kb < wr_lo + 15 + BAND) && (kb + 63 > wr_lo - BAND);

        if (active) {
            const uint32_t kbuf = S + 8192u + (uint32_t)(it & 1) * 16384u;
            const uint32_t vbuf = kbuf + 8192u;

            float s[8][4];
#pragma unroll
            for (int j = 0; j < 8; j++)
#pragma unroll
                for (int t = 0; t < 4; t++) s[j][t] = 0.f;

            // S = Q K^T (single term)
#pragma unroll
            for (int dc = 0; dc < 4; dc++) {
                const uint32_t colb = dc * 32 + ((lane >> 4) << 4);
#pragma unroll
                for (int np = 0; np < 4; np++) {
                    uint32_t ad = SWZ128((uint32_t)((np * 16 + (lane & 15)) * 128 + colb));
                    uint32_t bh4[4];
                    LDSM4(bh4, kbuf + ad);
#pragma unroll
                    for (int s0 = 0; s0 < 2; s0++)
                        MMAH(s[np * 2 + s0], qfh[dc], bh4[s0], bh4[s0 + 2]);
                }
            }

            float mt0 = -1e30f, mt1 = -1e30f;
#pragma unroll
            for (int j = 0; j < 8; j++) {
                const int kjb = kb + j * 8 + (lane & 3) * 2;
#pragma unroll
                for (int c = 0; c < 2; c++) {
                    const int dq0 = r0 - (kjb + c);
                    if (dq0 >= BAND || dq0 <= -BAND) s[j][c] = -1e9f;
                    const int dq1 = dq0 + 8;
                    if (dq1 >= BAND || dq1 <= -BAND) s[j][2 + c] = -1e9f;
                    mt0 = fmaxf(mt0, s[j][c]);
                    mt1 = fmaxf(mt1, s[j][2 + c]);
                }
            }
            mt0 = fmaxf(mt0, __shfl_xor_sync(0xffffffffu, mt0, 1));
            mt0 = fmaxf(mt0, __shfl_xor_sync(0xffffffffu, mt0, 2));
            mt1 = fmaxf(mt1, __shfl_xor_sync(0xffffffffu, mt1, 1));
            mt1 = fmaxf(mt1, __shfl_xor_sync(0xffffffffu, mt1, 2));
            const float mn0 = fmaxf(m0, mt0), mn1 = fmaxf(m1, mt1);
            const float a0 = __expf(m0 - mn0), a1 = __expf(m1 - mn1);
            m0 = mn0; m1 = mn1;
            float ls0 = 0.f, ls1 = 0.f;
#pragma unroll
            for (int j = 0; j < 8; j++)
#pragma unroll
                for (int c = 0; c < 2; c++) {
                    float p = __expf(s[j][c] - mn0);
                    s[j][c] = p; ls0 += p;
                    float p2 = __expf(s[j][2 + c] - mn1);
                    s[j][2 + c] = p2; ls1 += p2;
                }
            ls0 += __shfl_xor_sync(0xffffffffu, ls0, 1);
            ls0 += __shfl_xor_sync(0xffffffffu, ls0, 2);
            ls1 += __shfl_xor_sync(0xffffffffu, ls1, 1);
            ls1 += __shfl_xor_sync(0xffffffffu, ls1, 2);
            l0 = l0 * a0 + ls0;
            l1 = l1 * a1 + ls1;
#pragma unroll
            for (int j = 0; j < 8; j++) {
                o[j][0] *= a0; o[j][1] *= a0;
                o[j][2] *= a1; o[j][3] *= a1;
            }

            // O += (Ph+Pl) V
#pragma unroll
            for (int kc = 0; kc < 4; kc++) {
                uint32_t ph[4], pl[4];
                ph[0] = pack2h(s[2 * kc][0],     s[2 * kc][1],     pl[0]);
                ph[1] = pack2h(s[2 * kc][2],     s[2 * kc][3],     pl[1]);
                ph[2] = pack2h(s[2 * kc + 1][0], s[2 * kc + 1][1], pl[2]);
                ph[3] = pack2h(s[2 * kc + 1][2], s[2 * kc + 1][3], pl[3]);
                const uint32_t rowb = (uint32_t)((kc * 16 + (lane & 15)) * 128 + ((lane >> 4) << 4));
#pragma unroll
                for (int dg = 0; dg < 4; dg++) {
                    uint32_t ad = SWZ128(rowb + dg * 32);
                    uint32_t vh4[4];
                    LDSM4T(vh4, vbuf + ad);
                    MMAH(o[2 * dg],     ph, vh4[0], vh4[1]);
                    MMAH(o[2 * dg + 1], ph, vh4[2], vh4[3]);
                    MMAH(o[2 * dg],     pl, vh4[0], vh4[1]);
                    MMAH(o[2 * dg + 1], pl, vh4[2], vh4[3]);
                }
            }
        }

        __syncthreads();
        if (it + 2 < nt) issue_kv(it & 1, (kt_lo + it + 2) * 64);
    }

    const float inv0 = 1.f / l0, inv1 = 1.f / l1;
    const size_t e0 = ((size_t)(b * SS) + r0) * D_MODEL + h * DK + (lane & 3) * 2;
    const size_t e1 = e0 + 8 * D_MODEL;
#pragma unroll
    for (int j = 0; j < 8; j++) {
        *(uint32_t*)(g_aoh + e0 + j * 8) = pack2s(o[j][0] * inv0, o[j][1] * inv0);
        *(uint32_t*)(g_aoh + e1 + j * 8) = pack2s(o[j][2] * inv1, o[j][3] * inv1);
    }
}

// ---------------------------------------------------------------------------

extern "C" void kernel_launch(void* const* d_in, const int* in_sizes, int n_in,
                              void* d_out, int out_size)
{
    const float* x  = (const float*)d_in[0];
    const float* Wq = (const float*)d_in[1];
    const float* bq = (const float*)d_in[2];
    const float* Wk = (const float*)d_in[3];
    const float* bk = (const float*)d_in[4];
    const float* Wv = (const float*)d_in[5];
    const float* bv = (const float*)d_in[6];
    const float* Wo = (const float*)d_in[7];
    const float* bo = (const float*)d_in[8];
    float* out = (float*)d_out;

    const int GSM = 4 * 16384 + 1024;           // 66560 B/CTA -> 2 CTAs/SM
    const int ASM = 8192 + 2 * 16384 + 1024;    // 41984 B/CTA
    static bool attr_done = false;
    if (!attr_done) {
        cudaFuncSetAttribute(tc_gemm, cudaFuncAttributeMaxDynamicSharedMemorySize, GSM);
        cudaFuncSetAttribute(fa_attn, cudaFuncAttributeMaxDynamicSharedMemorySize, ASM);
        attr_done = true;
    }

    const int NCVT = NX4 + 4 * NW4;
    cvt_all<<<(NCVT + 255) / 256, 256>>>((const float4*)x, (const float4*)Wq,
                                         (const float4*)Wk, (const float4*)Wv,
                                         (const float4*)Wo);

    tc_gemm<<<dim3(D_MODEL / 128, M_TOT / 128, 3), 128, GSM>>>(0, bq, bk, bv, nullptr);
    fa_attn<<<dim3(SS / 64, NH, BB), 128, ASM>>>();
    tc_gemm<<<dim3(D_MODEL / 128, M_TOT / 128, 1), 128, GSM>>>(1, bo, bo, bo, out);
}

// round 16
// speedup vs baseline: 2.3028x; 1.0297x over previous
#include <cuda_runtime.h>
#include <cuda_fp16.h>
#include <cstdint>
#include <math.h>

#define D_MODEL 1024
#define NH 16
#define DK 64
#define BAND 100
#define BB 2
#define SS 2048
#define M_TOT (BB * SS)
#define DM2 (D_MODEL * D_MODEL)

// ---------------- scratch (device globals; no allocs allowed) ----------------
__device__ __align__(256) __half g_qh[BB * NH * SS * DK];   // Q (scaled 0.125)
__device__ __align__(256) __half g_kh[BB * NH * SS * DK];   // K
__device__ __align__(256) __half g_vh[BB * NH * SS * DK];   // V
__device__ __align__(256) __half g_xh[M_TOT * D_MODEL];     // x fp16
__device__ __align__(256) __half g_wh[4 * DM2];             // W fp16 (4 slots)
__device__ __align__(256) __half g_aoh[M_TOT * D_MODEL];    // attn out fp16

// ---------------- helpers ----------------
__device__ __forceinline__ uint32_t s2u(const void* p) {
    uint32_t a;
    asm("{ .reg .u64 t; cvta.to.shared.u64 t, %1; cvt.u32.u64 %0, t; }" : "=r"(a) : "l"(p));
    return a;
}

#define SWZ64(o)  ((o) ^ (((o) >> 3) & 0x30))
#define SWZ128(o) ((o) ^ (((o) >> 3) & 0x70))

#define CP16(dst, src) \
    asm volatile("cp.async.cg.shared.global [%0], [%1], 16;" :: "r"(dst), "l"(src))
#define CP_COMMIT() asm volatile("cp.async.commit_group;" ::: "memory")

#define LDSM4(r, addr) \
    asm volatile("ldmatrix.sync.aligned.m8n8.x4.shared.b16 {%0,%1,%2,%3}, [%4];" \
                 : "=r"((r)[0]), "=r"((r)[1]), "=r"((r)[2]), "=r"((r)[3]) : "r"(addr))
#define LDSM4T(r, addr) \
    asm volatile("ldmatrix.sync.aligned.m8n8.x4.trans.shared.b16 {%0,%1,%2,%3}, [%4];" \
                 : "=r"((r)[0]), "=r"((r)[1]), "=r"((r)[2]), "=r"((r)[3]) : "r"(addr))

#define MMAH(d, a, bx, by) \
    asm volatile("mma.sync.aligned.m16n8k16.row.col.f32.f16.f16.f32 " \
                 "{%0,%1,%2,%3}, {%4,%5,%6,%7}, {%8,%9}, {%0,%1,%2,%3};" \
                 : "+f"((d)[0]), "+f"((d)[1]), "+f"((d)[2]), "+f"((d)[3]) \
                 : "r"((a)[0]), "r"((a)[1]), "r"((a)[2]), "r"((a)[3]), "r"(bx), "r"(by))

__device__ __forceinline__ uint32_t pack2s(float a, float b) {
    __half2 h = __floats2half2_rn(a, b);
    return *reinterpret_cast<uint32_t*>(&h);
}

// ---------------- fp32 -> fp16 conversions (single launch) ----------------
#define NX4 (M_TOT * D_MODEL / 4)
#define NW4 (DM2 / 4)

__global__ void cvt_all(const float4* __restrict__ x,
                        const float4* __restrict__ wq, const float4* __restrict__ wk,
                        const float4* __restrict__ wv, const float4* __restrict__ wo)
{
    int i = blockIdx.x * blockDim.x + threadIdx.x;
    if (i < NX4) {
        float4 v = x[i];
        uint2 hv;
        hv.x = pack2s(v.x, v.y);
        hv.y = pack2s(v.z, v.w);
        ((uint2*)g_xh)[i] = hv;
    } else {
        int j = i - NX4;
        if (j >= 4 * NW4) return;
        int slot = j >> 18;
        int k = j & (NW4 - 1);
        const float4* src = (slot == 0) ? wq : (slot == 1) ? wk : (slot == 2) ? wv : wo;
        float4 v = src[k];
        uint2 hv;
        hv.x = pack2s(v.x, v.y);
        hv.y = pack2s(v.z, v.w);
        ((uint2*)g_wh)[j] = hv;
    }
}

// ---------------------------------------------------------------------------
// HMMA fp16 GEMM, single-term: D = A @ W^T + bias.
// CTA 128x128, 4 warps (2x2, warp 64x64), K-chunk 32, cp.async 4-stage
// (wait_group 2), 128 threads, one __syncthreads per iteration.
// stage (16KB): A[128x64B]@0  B[128x64B]@8192
// ---------------------------------------------------------------------------
__global__ __launch_bounds__(128, 2) void tc_gemm(
    int mode, const float* __restrict__ b0, const float* __restrict__ b1,
    const float* __restrict__ b2, float* outp)
{
    extern __shared__ char dsm[];
    uint32_t raw = s2u(dsm);
    const uint32_t S = (raw + 1023u) & ~1023u;

    const int tid = threadIdx.x;
    const int lane = tid & 31;
    const int wid = tid >> 5;
    const int wm = wid >> 1;
    const int wn = wid & 1;
    const int bm = blockIdx.y * 128;
    const int bn = blockIdx.x * 128;
    const int z = blockIdx.z;

    const __half *Ahp, *Whp;
    const float* bias;
    if (mode == 0) {
        Ahp = g_xh;
        Whp = g_wh + (size_t)z * DM2;
        bias = (z == 0) ? b0 : (z == 1) ? b1 : b2;
    } else {
        Ahp = g_aoh;
        Whp = g_wh + 3 * (size_t)DM2;
        bias = b0;
    }

    const int crow = tid >> 2;        // 0..31
    const int ccol = (tid & 3) * 16;
    uint32_t adst[4];
#pragma unroll
    for (int p = 0; p < 4; p++)
        adst[p] = SWZ64((uint32_t)((crow + 32 * p) * 64 + ccol));

    auto issue = [&](int stg, int kt) {
        uint32_t sb = S + (uint32_t)stg * 16384u;
        size_t ga = (size_t)(bm + crow) * D_MODEL + kt + (ccol >> 1);
        size_t gb = (size_t)(bn + crow) * D_MODEL + kt + (ccol >> 1);
#pragma unroll
        for (int p = 0; p < 4; p++) {
            CP16(sb + adst[p],        Ahp + ga + (size_t)(32 * p) * D_MODEL);
            CP16(sb + 8192 + adst[p], Whp + gb + (size_t)(32 * p) * D_MODEL);
        }
        CP_COMMIT();
    };

    // ldmatrix offsets (kh=0); kh=1 = XOR 32 (bit5 pre-swizzle, unaffected by SWZ64)
    uint32_t aoff[4], boff[4];
#pragma unroll
    for (int mf = 0; mf < 4; mf++) {
        int r = wm * 64 + mf * 16 + (lane & 15);
        aoff[mf] = SWZ64((uint32_t)(r * 64 + ((lane >> 4) << 4)));
    }
#pragma unroll
    for (int nf = 0; nf < 4; nf++) {
        int r = wn * 64 + nf * 16 + (lane & 15);
        boff[nf] = 8192u + SWZ64((uint32_t)(r * 64 + ((lane >> 4) << 4)));
    }

    float acc[4][8][4];
#pragma unroll
    for (int mf = 0; mf < 4; mf++)
#pragma unroll
        for (int j = 0; j < 8; j++)
#pragma unroll
            for (int t = 0; t < 4; t++) acc[mf][j][t] = 0.f;

    issue(0, 0);
    issue(1, 32);
    issue(2, 64);

    for (int i = 0; i < 32; i++) {
        asm volatile("cp.async.wait_group 2;" ::: "memory");
        __syncthreads();
        // This sync also proves every warp finished iteration i-1's compute on
        // buffer (i-1)&3 == (i+3)&3, so issuing into it now is race-free.
        const uint32_t sb = S + (uint32_t)(((uint32_t)i) & 3u) * 16384u;
        if (i + 3 < 32) issue((i + 3) & 3, (i + 3) * 32);
        else CP_COMMIT();

#pragma unroll
        for (int kh = 0; kh < 2; kh++) {
            const uint32_t xk = (uint32_t)(kh * 32);
            uint32_t ah[4][4];
#pragma unroll
            for (int mf = 0; mf < 4; mf++)
                LDSM4(ah[mf], sb + (aoff[mf] ^ xk));
#pragma unroll
            for (int nf = 0; nf < 4; nf++) {
                uint32_t bh[4];
                LDSM4(bh, sb + (boff[nf] ^ xk));
#pragma unroll
                for (int mf = 0; mf < 4; mf++)
#pragma unroll
                    for (int s0 = 0; s0 < 2; s0++)
                        MMAH(acc[mf][nf * 2 + s0], ah[mf], bh[s0], bh[s0 + 2]);
            }
        }
    }

    const int r0 = lane >> 2;
    const int c0 = (lane & 3) << 1;
#pragma unroll
    for (int mf = 0; mf < 4; mf++) {
        const int m_ = bm + wm * 64 + mf * 16 + r0;
#pragma unroll
        for (int j = 0; j < 8; j++) {
            const int n_ = bn + wn * 64 + j * 8 + c0;
            const float bx = bias[n_], by = bias[n_ + 1];
            float v00 = acc[mf][j][0] + bx, v01 = acc[mf][j][1] + by;
            float v10 = acc[mf][j][2] + bx, v11 = acc[mf][j][3] + by;
            if (mode == 0) {
                const int b_ = m_ >> 11, s_ = m_ & (SS - 1);
                size_t idx = ((((size_t)b_ * NH + (n_ >> 6)) * SS) + s_) * DK + (n_ & 63);
                const float sc = (z == 0) ? 0.125f : 1.f;
                __half* dstp = (z == 0) ? g_qh : (z == 1) ? g_kh : g_vh;
                *(uint32_t*)(dstp + idx) = pack2s(v00 * sc, v01 * sc);
                *(uint32_t*)(dstp + idx + 8 * DK) = pack2s(v10 * sc, v11 * sc);
            } else {
                float* p = outp + (size_t)m_ * D_MODEL + n_;
                *(float2*)p = make_float2(v00, v01);
                *(float2*)(p + 8 * D_MODEL) = make_float2(v10, v11);
            }
        }
    }
}

// ---------------------------------------------------------------------------
// fp16 tensor-core banded flash attention, fully single-term (Q and P fp16).
// smem: Q@0 (8KB) | 2 stages x (K 8K + V 8K) at 8192.
// ---------------------------------------------------------------------------
__global__ __launch_bounds__(128, 3) void fa_attn()
{
    extern __shared__ char dsm[];
    uint32_t raw = s2u(dsm);
    const uint32_t S = (raw + 1023u) & ~1023u;

    const int tid = threadIdx.x;
    const int lane = tid & 31;
    const int wid = tid >> 5;
    const int q0 = blockIdx.x * 64;
    const int h = blockIdx.y;
    const int b = blockIdx.z;

    const size_t base = (((size_t)b * NH + h) * SS) * DK;
    const __half* qh = g_qh + base;
    const __half* kh = g_kh + base;
    const __half* vh = g_vh + base;

    int klo = q0 - (BAND - 1); if (klo < 0) klo = 0;
    int khi = q0 + 63 + (BAND - 1); if (khi > SS - 1) khi = SS - 1;
    const int kt_lo = klo >> 6;
    const int nt = (khi >> 6) - kt_lo + 1;

    auto issue_kv = [&](int st, int kb) {
        uint32_t sb = S + 8192u + (uint32_t)st * 16384u;
#pragma unroll
        for (int i = 0; i < 4; i++) {
            int idx = i * 128 + tid;
            int row = idx >> 3;
            int chb = (idx & 7) * 16;
            uint32_t dsw = SWZ128((uint32_t)(row * 128 + chb));
            size_t g = (size_t)(kb + row) * DK + (chb >> 1);
            CP16(sb + dsw,        kh + g);
            CP16(sb + 8192 + dsw, vh + g);
        }
        CP_COMMIT();
    };

    // Q tile: 8KB = 512 16B-chunks over 128 threads = 4 each
#pragma unroll
    for (int i = 0; i < 4; i++) {
        int idx = i * 128 + tid;
        int row = idx >> 3;
        int chb = (idx & 7) * 16;
        uint32_t dsw = SWZ128((uint32_t)(row * 128 + chb));
        size_t g = (size_t)(q0 + row) * DK + (chb >> 1);
        CP16(S + dsw, qh + g);
    }
    issue_kv(0, kt_lo * 64);
    if (nt > 1) issue_kv(1, (kt_lo + 1) * 64);

    uint32_t qfh[4][4];
    float o[8][4];
#pragma unroll
    for (int j = 0; j < 8; j++)
#pragma unroll
        for (int t = 0; t < 4; t++) o[j][t] = 0.f;
    float m0 = -1e30f, m1 = -1e30f, l0 = 0.f, l1 = 0.f;

    const int wr_lo = q0 + wid * 16;
    const int r0 = wr_lo + (lane >> 2);

    for (int it = 0; it < nt; it++) {
        if (it + 1 < nt) asm volatile("cp.async.wait_group 1;" ::: "memory");
        else             asm volatile("cp.async.wait_group 0;" ::: "memory");
        __syncthreads();

        if (it == 0) {
            const int qr = wid * 16 + (lane & 15);
#pragma unroll
            for (int dc = 0; dc < 4; dc++) {
                uint32_t ad = SWZ128((uint32_t)(qr * 128 + dc * 32 + ((lane >> 4) << 4)));
                LDSM4(qfh[dc], S + ad);
            }
        }

        const int kb = (kt_lo + it) * 64;
        const bool active = (kb < wr_lo + 15 + BAND) && (kb + 63 > wr_lo - BAND);

        if (active) {
            const uint32_t kbuf = S + 8192u + (uint32_t)(it & 1) * 16384u;
            const uint32_t vbuf = kbuf + 8192u;

            float s[8][4];
#pragma unroll
            for (int j = 0; j < 8; j++)
#pragma unroll
                for (int t = 0; t < 4; t++) s[j][t] = 0.f;

            // S = Q K^T
#pragma unroll
            for (int dc = 0; dc < 4; dc++) {
                const uint32_t colb = dc * 32 + ((lane >> 4) << 4);
#pragma unroll
                for (int np = 0; np < 4; np++) {
                    uint32_t ad = SWZ128((uint32_t)((np * 16 + (lane & 15)) * 128 + colb));
                    uint32_t bh4[4];
                    LDSM4(bh4, kbuf + ad);
#pragma unroll
                    for (int s0 = 0; s0 < 2; s0++)
                        MMAH(s[np * 2 + s0], qfh[dc], bh4[s0], bh4[s0 + 2]);
                }
            }

            float mt0 = -1e30f, mt1 = -1e30f;
#pragma unroll
            for (int j = 0; j < 8; j++) {
                const int kjb = kb + j * 8 + (lane & 3) * 2;
#pragma unroll
                for (int c = 0; c < 2; c++) {
                    const int dq0 = r0 - (kjb + c);
                    if (dq0 >= BAND || dq0 <= -BAND) s[j][c] = -1e9f;
                    const int dq1 = dq0 + 8;
                    if (dq1 >= BAND || dq1 <= -BAND) s[j][2 + c] = -1e9f;
                    mt0 = fmaxf(mt0, s[j][c]);
                    mt1 = fmaxf(mt1, s[j][2 + c]);
                }
            }
            mt0 = fmaxf(mt0, __shfl_xor_sync(0xffffffffu, mt0, 1));
            mt0 = fmaxf(mt0, __shfl_xor_sync(0xffffffffu, mt0, 2));
            mt1 = fmaxf(mt1, __shfl_xor_sync(0xffffffffu, mt1, 1));
            mt1 = fmaxf(mt1, __shfl_xor_sync(0xffffffffu, mt1, 2));
            const float mn0 = fmaxf(m0, mt0), mn1 = fmaxf(m1, mt1);
            const float a0 = __expf(m0 - mn0), a1 = __expf(m1 - mn1);
            m0 = mn0; m1 = mn1;
            float ls0 = 0.f, ls1 = 0.f;
#pragma unroll
            for (int j = 0; j < 8; j++)
#pragma unroll
                for (int c = 0; c < 2; c++) {
                    float p = __expf(s[j][c] - mn0);
                    s[j][c] = p; ls0 += p;
                    float p2 = __expf(s[j][2 + c] - mn1);
                    s[j][2 + c] = p2; ls1 += p2;
                }
            ls0 += __shfl_xor_sync(0xffffffffu, ls0, 1);
            ls0 += __shfl_xor_sync(0xffffffffu, ls0, 2);
            ls1 += __shfl_xor_sync(0xffffffffu, ls1, 1);
            ls1 += __shfl_xor_sync(0xffffffffu, ls1, 2);
            l0 = l0 * a0 + ls0;
            l1 = l1 * a1 + ls1;
#pragma unroll
            for (int j = 0; j < 8; j++) {
                o[j][0] *= a0; o[j][1] *= a0;
                o[j][2] *= a1; o[j][3] *= a1;
            }

            // O += P V (P single fp16; rounding ~eps/sqrt(3) rel on O)
#pragma unroll
            for (int kc = 0; kc < 4; kc++) {
                uint32_t ph[4];
                ph[0] = pack2s(s[2 * kc][0],     s[2 * kc][1]);
                ph[1] = pack2s(s[2 * kc][2],     s[2 * kc][3]);
                ph[2] = pack2s(s[2 * kc + 1][0], s[2 * kc + 1][1]);
                ph[3] = pack2s(s[2 * kc + 1][2], s[2 * kc + 1][3]);
                const uint32_t rowb = (uint32_t)((kc * 16 + (lane & 15)) * 128 + ((lane >> 4) << 4));
#pragma unroll
                for (int dg = 0; dg < 4; dg++) {
                    uint32_t ad = SWZ128(rowb + dg * 32);
                    uint32_t vh4[4];
                    LDSM4T(vh4, vbuf + ad);
                    MMAH(o[2 * dg],     ph, vh4[0], vh4[1]);
                    MMAH(o[2 * dg + 1], ph, vh4[2], vh4[3]);
                }
            }
        }

        __syncthreads();
        if (it + 2 < nt) issue_kv(it & 1, (kt_lo + it + 2) * 64);
    }

    const float inv0 = 1.f / l0, inv1 = 1.f / l1;
    const size_t e0 = ((size_t)(b * SS) + r0) * D_MODEL + h * DK + (lane & 3) * 2;
    const size_t e1 = e0 + 8 * D_MODEL;
#pragma unroll
    for (int j = 0; j < 8; j++) {
        *(uint32_t*)(g_aoh + e0 + j * 8) = pack2s(o[j][0] * inv0, o[j][1] * inv0);
        *(uint32_t*)(g_aoh + e1 + j * 8) = pack2s(o[j][2] * inv1, o[j][3] * inv1);
    }
}

// ---------------------------------------------------------------------------

extern "C" void kernel_launch(void* const* d_in, const int* in_sizes, int n_in,
                              void* d_out, int out_size)
{
    const float* x  = (const float*)d_in[0];
    const float* Wq = (const float*)d_in[1];
    const float* bq = (const float*)d_in[2];
    const float* Wk = (const float*)d_in[3];
    const float* bk = (const float*)d_in[4];
    const float* Wv = (const float*)d_in[5];
    const float* bv = (const float*)d_in[6];
    const float* Wo = (const float*)d_in[7];
    const float* bo = (const float*)d_in[8];
    float* out = (float*)d_out;

    const int GSM = 4 * 16384 + 1024;           // 66560 B/CTA -> 2 CTAs/SM
    const int ASM = 8192 + 2 * 16384 + 1024;    // 41984 B/CTA
    static bool attr_done = false;
    if (!attr_done) {
        cudaFuncSetAttribute(tc_gemm, cudaFuncAttributeMaxDynamicSharedMemorySize, GSM);
        cudaFuncSetAttribute(fa_attn, cudaFuncAttributeMaxDynamicSharedMemorySize, ASM);
        attr_done = true;
    }

    const int NCVT = NX4 + 4 * NW4;
    cvt_all<<<(NCVT + 255) / 256, 256>>>((const float4*)x, (const float4*)Wq,
                                         (const float4*)Wk, (const float4*)Wv,
                                         (const float4*)Wo);

    tc_gemm<<<dim3(D_MODEL / 128, M_TOT / 128, 3), 128, GSM>>>(0, bq, bk, bv, nullptr);
    fa_attn<<<dim3(SS / 64, NH, BB), 128, ASM>>>();
    tc_gemm<<<dim3(D_MODEL / 128, M_TOT / 128, 1), 128, GSM>>>(1, bo, bo, bo, out);
}

// round 17
// speedup vs baseline: 2.3263x; 1.0102x over previous
#include <cuda_runtime.h>
#include <cuda_fp16.h>
#include <cstdint>
#include <math.h>

#define D_MODEL 1024
#define NH 16
#define DK 64
#define BAND 100
#define BB 2
#define SS 2048
#define M_TOT (BB * SS)
#define DM2 (D_MODEL * D_MODEL)

// Q scale folded with log2(e): logits come out of QK^T already in log2 domain.
#define QSCALE 0.18033688011112042f   // 0.125 * log2(e)

// ---------------- scratch (device globals; no allocs allowed) ----------------
__device__ __align__(256) __half g_qh[BB * NH * SS * DK];   // Q (scaled QSCALE)
__device__ __align__(256) __half g_kh[BB * NH * SS * DK];   // K
__device__ __align__(256) __half g_vh[BB * NH * SS * DK];   // V
__device__ __align__(256) __half g_xh[M_TOT * D_MODEL];     // x fp16
__device__ __align__(256) __half g_wh[4 * DM2];             // W fp16 (4 slots)
__device__ __align__(256) __half g_aoh[M_TOT * D_MODEL];    // attn out fp16

// ---------------- helpers ----------------
__device__ __forceinline__ uint32_t s2u(const void* p) {
    uint32_t a;
    asm("{ .reg .u64 t; cvta.to.shared.u64 t, %1; cvt.u32.u64 %0, t; }" : "=r"(a) : "l"(p));
    return a;
}

#define SWZ64(o)  ((o) ^ (((o) >> 3) & 0x30))
#define SWZ128(o) ((o) ^ (((o) >> 3) & 0x70))

#define CP16(dst, src) \
    asm volatile("cp.async.cg.shared.global [%0], [%1], 16;" :: "r"(dst), "l"(src))
#define CP_COMMIT() asm volatile("cp.async.commit_group;" ::: "memory")

#define LDSM4(r, addr) \
    asm volatile("ldmatrix.sync.aligned.m8n8.x4.shared.b16 {%0,%1,%2,%3}, [%4];" \
                 : "=r"((r)[0]), "=r"((r)[1]), "=r"((r)[2]), "=r"((r)[3]) : "r"(addr))
#define LDSM4T(r, addr) \
    asm volatile("ldmatrix.sync.aligned.m8n8.x4.trans.shared.b16 {%0,%1,%2,%3}, [%4];" \
                 : "=r"((r)[0]), "=r"((r)[1]), "=r"((r)[2]), "=r"((r)[3]) : "r"(addr))

#define MMAH(d, a, bx, by) \
    asm volatile("mma.sync.aligned.m16n8k16.row.col.f32.f16.f16.f32 " \
                 "{%0,%1,%2,%3}, {%4,%5,%6,%7}, {%8,%9}, {%0,%1,%2,%3};" \
                 : "+f"((d)[0]), "+f"((d)[1]), "+f"((d)[2]), "+f"((d)[3]) \
                 : "r"((a)[0]), "r"((a)[1]), "r"((a)[2]), "r"((a)[3]), "r"(bx), "r"(by))

__device__ __forceinline__ uint32_t pack2s(float a, float b) {
    __half2 h = __floats2half2_rn(a, b);
    return *reinterpret_cast<uint32_t*>(&h);
}

// ---------------- fp32 -> fp16 conversions (single launch) ----------------
#define NX4 (M_TOT * D_MODEL / 4)
#define NW4 (DM2 / 4)

__global__ void cvt_all(const float4* __restrict__ x,
                        const float4* __restrict__ wq, const float4* __restrict__ wk,
                        const float4* __restrict__ wv, const float4* __restrict__ wo)
{
    int i = blockIdx.x * blockDim.x + threadIdx.x;
    if (i < NX4) {
        float4 v = x[i];
        uint2 hv;
        hv.x = pack2s(v.x, v.y);
        hv.y = pack2s(v.z, v.w);
        ((uint2*)g_xh)[i] = hv;
    } else {
        int j = i - NX4;
        if (j >= 4 * NW4) return;
        int slot = j >> 18;
        int k = j & (NW4 - 1);
        const float4* src = (slot == 0) ? wq : (slot == 1) ? wk : (slot == 2) ? wv : wo;
        float4 v = src[k];
        uint2 hv;
        hv.x = pack2s(v.x, v.y);
        hv.y = pack2s(v.z, v.w);
        ((uint2*)g_wh)[j] = hv;
    }
}

// ---------------------------------------------------------------------------
// HMMA fp16 GEMM, single-term: D = A @ W^T + bias.
// CTA 128x128, 4 warps (2x2, warp 64x64), K-chunk 32, cp.async 4-stage
// (wait_group 2), 128 threads, one __syncthreads per iteration.
// stage (16KB): A[128x64B]@0  B[128x64B]@8192
// ---------------------------------------------------------------------------
__global__ __launch_bounds__(128, 2) void tc_gemm(
    int mode, const float* __restrict__ b0, const float* __restrict__ b1,
    const float* __restrict__ b2, float* outp)
{
    extern __shared__ char dsm[];
    uint32_t raw = s2u(dsm);
    const uint32_t S = (raw + 1023u) & ~1023u;

    const int tid = threadIdx.x;
    const int lane = tid & 31;
    const int wid = tid >> 5;
    const int wm = wid >> 1;
    const int wn = wid & 1;
    const int bm = blockIdx.y * 128;
    const int bn = blockIdx.x * 128;
    const int z = blockIdx.z;

    const __half *Ahp, *Whp;
    const float* bias;
    if (mode == 0) {
        Ahp = g_xh;
        Whp = g_wh + (size_t)z * DM2;
        bias = (z == 0) ? b0 : (z == 1) ? b1 : b2;
    } else {
        Ahp = g_aoh;
        Whp = g_wh + 3 * (size_t)DM2;
        bias = b0;
    }

    const int crow = tid >> 2;        // 0..31
    const int ccol = (tid & 3) * 16;
    uint32_t adst[4];
#pragma unroll
    for (int p = 0; p < 4; p++)
        adst[p] = SWZ64((uint32_t)((crow + 32 * p) * 64 + ccol));

    auto issue = [&](int stg, int kt) {
        uint32_t sb = S + (uint32_t)stg * 16384u;
        size_t ga = (size_t)(bm + crow) * D_MODEL + kt + (ccol >> 1);
        size_t gb = (size_t)(bn + crow) * D_MODEL + kt + (ccol >> 1);
#pragma unroll
        for (int p = 0; p < 4; p++) {
            CP16(sb + adst[p],        Ahp + ga + (size_t)(32 * p) * D_MODEL);
            CP16(sb + 8192 + adst[p], Whp + gb + (size_t)(32 * p) * D_MODEL);
        }
        CP_COMMIT();
    };

    // ldmatrix offsets (kh=0); kh=1 = XOR 32 (bit5 pre-swizzle, unaffected by SWZ64)
    uint32_t aoff[4], boff[4];
#pragma unroll
    for (int mf = 0; mf < 4; mf++) {
        int r = wm * 64 + mf * 16 + (lane & 15);
        aoff[mf] = SWZ64((uint32_t)(r * 64 + ((lane >> 4) << 4)));
    }
#pragma unroll
    for (int nf = 0; nf < 4; nf++) {
        int r = wn * 64 + nf * 16 + (lane & 15);
        boff[nf] = 8192u + SWZ64((uint32_t)(r * 64 + ((lane >> 4) << 4)));
    }

    float acc[4][8][4];
#pragma unroll
    for (int mf = 0; mf < 4; mf++)
#pragma unroll
        for (int j = 0; j < 8; j++)
#pragma unroll
            for (int t = 0; t < 4; t++) acc[mf][j][t] = 0.f;

    issue(0, 0);
    issue(1, 32);
    issue(2, 64);

    for (int i = 0; i < 32; i++) {
        asm volatile("cp.async.wait_group 2;" ::: "memory");
        __syncthreads();
        // This sync also proves every warp finished iteration i-1's compute on
        // buffer (i-1)&3 == (i+3)&3, so issuing into it now is race-free.
        const uint32_t sb = S + (uint32_t)(((uint32_t)i) & 3u) * 16384u;
        if (i + 3 < 32) issue((i + 3) & 3, (i + 3) * 32);
        else CP_COMMIT();

#pragma unroll
        for (int kh = 0; kh < 2; kh++) {
            const uint32_t xk = (uint32_t)(kh * 32);
            uint32_t ah[4][4];
#pragma unroll
            for (int mf = 0; mf < 4; mf++)
                LDSM4(ah[mf], sb + (aoff[mf] ^ xk));
#pragma unroll
            for (int nf = 0; nf < 4; nf++) {
                uint32_t bh[4];
                LDSM4(bh, sb + (boff[nf] ^ xk));
#pragma unroll
                for (int mf = 0; mf < 4; mf++)
#pragma unroll
                    for (int s0 = 0; s0 < 2; s0++)
                        MMAH(acc[mf][nf * 2 + s0], ah[mf], bh[s0], bh[s0 + 2]);
            }
        }
    }

    const int r0 = lane >> 2;
    const int c0 = (lane & 3) << 1;
#pragma unroll
    for (int mf = 0; mf < 4; mf++) {
        const int m_ = bm + wm * 64 + mf * 16 + r0;
#pragma unroll
        for (int j = 0; j < 8; j++) {
            const int n_ = bn + wn * 64 + j * 8 + c0;
            const float bx = bias[n_], by = bias[n_ + 1];
            float v00 = acc[mf][j][0] + bx, v01 = acc[mf][j][1] + by;
            float v10 = acc[mf][j][2] + bx, v11 = acc[mf][j][3] + by;
            if (mode == 0) {
                const int b_ = m_ >> 11, s_ = m_ & (SS - 1);
                size_t idx = ((((size_t)b_ * NH + (n_ >> 6)) * SS) + s_) * DK + (n_ & 63);
                const float sc = (z == 0) ? QSCALE : 1.f;
                __half* dstp = (z == 0) ? g_qh : (z == 1) ? g_kh : g_vh;
                *(uint32_t*)(dstp + idx) = pack2s(v00 * sc, v01 * sc);
                *(uint32_t*)(dstp + idx + 8 * DK) = pack2s(v10 * sc, v11 * sc);
            } else {
                float* p = outp + (size_t)m_ * D_MODEL + n_;
                *(float2*)p = make_float2(v00, v01);
                *(float2*)(p + 8 * D_MODEL) = make_float2(v10, v11);
            }
        }
    }
}

// ---------------------------------------------------------------------------
// fp16 tensor-core banded flash attention; logits in log2 domain (exp2f
// softmax — Q carries the log2(e) factor). Q and P single-term fp16.
// smem: Q@0 (8KB) | 2 stages x (K 8K + V 8K) at 8192.
// ---------------------------------------------------------------------------
__global__ __launch_bounds__(128, 3) void fa_attn()
{
    extern __shared__ char dsm[];
    uint32_t raw = s2u(dsm);
    const uint32_t S = (raw + 1023u) & ~1023u;

    const int tid = threadIdx.x;
    const int lane = tid & 31;
    const int wid = tid >> 5;
    const int q0 = blockIdx.x * 64;
    const int h = blockIdx.y;
    const int b = blockIdx.z;

    const size_t base = (((size_t)b * NH + h) * SS) * DK;
    const __half* qh = g_qh + base;
    const __half* kh = g_kh + base;
    const __half* vh = g_vh + base;

    int klo = q0 - (BAND - 1); if (klo < 0) klo = 0;
    int khi = q0 + 63 + (BAND - 1); if (khi > SS - 1) khi = SS - 1;
    const int kt_lo = klo >> 6;
    const int nt = (khi >> 6) - kt_lo + 1;

    auto issue_kv = [&](int st, int kb) {
        uint32_t sb = S + 8192u + (uint32_t)st * 16384u;
#pragma unroll
        for (int i = 0; i < 4; i++) {
            int idx = i * 128 + tid;
            int row = idx >> 3;
            int chb = (idx & 7) * 16;
            uint32_t dsw = SWZ128((uint32_t)(row * 128 + chb));
            size_t g = (size_t)(kb + row) * DK + (chb >> 1);
            CP16(sb + dsw,        kh + g);
            CP16(sb + 8192 + dsw, vh + g);
        }
        CP_COMMIT();
    };

    // Q tile: 8KB = 512 16B-chunks over 128 threads = 4 each
#pragma unroll
    for (int i = 0; i < 4; i++) {
        int idx = i * 128 + tid;
        int row = idx >> 3;
        int chb = (idx & 7) * 16;
        uint32_t dsw = SWZ128((uint32_t)(row * 128 + chb));
        size_t g = (size_t)(q0 + row) * DK + (chb >> 1);
        CP16(S + dsw, qh + g);
    }
    issue_kv(0, kt_lo * 64);
    if (nt > 1) issue_kv(1, (kt_lo + 1) * 64);

    uint32_t qfh[4][4];
    float o[8][4];
#pragma unroll
    for (int j = 0; j < 8; j++)
#pragma unroll
        for (int t = 0; t < 4; t++) o[j][t] = 0.f;
    float m0 = -1e30f, m1 = -1e30f, l0 = 0.f, l1 = 0.f;

    const int wr_lo = q0 + wid * 16;
    const int r0 = wr_lo + (lane >> 2);

    for (int it = 0; it < nt; it++) {
        if (it + 1 < nt) asm volatile("cp.async.wait_group 1;" ::: "memory");
        else             asm volatile("cp.async.wait_group 0;" ::: "memory");
        __syncthreads();

        if (it == 0) {
            const int qr = wid * 16 + (lane & 15);
#pragma unroll
            for (int dc = 0; dc < 4; dc++) {
                uint32_t ad = SWZ128((uint32_t)(qr * 128 + dc * 32 + ((lane >> 4) << 4)));
                LDSM4(qfh[dc], S + ad);
            }
        }

        const int kb = (kt_lo + it) * 64;
        const bool active = (kb < wr_lo + 15 + BAND) && (kb + 63 > wr_lo - BAND);

        if (active) {
            const uint32_t kbuf = S + 8192u + (uint32_t)(it & 1) * 16384u;
            const uint32_t vbuf = kbuf + 8192u;

            float s[8][4];
#pragma unroll
            for (int j = 0; j < 8; j++)
#pragma unroll
                for (int t = 0; t < 4; t++) s[j][t] = 0.f;

            // S = Q K^T  (already scaled by 0.125*log2e -> log2-domain logits)
#pragma unroll
            for (int dc = 0; dc < 4; dc++) {
                const uint32_t colb = dc * 32 + ((lane >> 4) << 4);
#pragma unroll
                for (int np = 0; np < 4; np++) {
                    uint32_t ad = SWZ128((uint32_t)((np * 16 + (lane & 15)) * 128 + colb));
                    uint32_t bh4[4];
                    LDSM4(bh4, kbuf + ad);
#pragma unroll
                    for (int s0 = 0; s0 < 2; s0++)
                        MMAH(s[np * 2 + s0], qfh[dc], bh4[s0], bh4[s0 + 2]);
                }
            }

            float mt0 = -1e30f, mt1 = -1e30f;
#pragma unroll
            for (int j = 0; j < 8; j++) {
                const int kjb = kb + j * 8 + (lane & 3) * 2;
#pragma unroll
                for (int c = 0; c < 2; c++) {
                    const int dq0 = r0 - (kjb + c);
                    if (dq0 >= BAND || dq0 <= -BAND) s[j][c] = -1e9f;
                    const int dq1 = dq0 + 8;
                    if (dq1 >= BAND || dq1 <= -BAND) s[j][2 + c] = -1e9f;
                    mt0 = fmaxf(mt0, s[j][c]);
                    mt1 = fmaxf(mt1, s[j][2 + c]);
                }
            }
            mt0 = fmaxf(mt0, __shfl_xor_sync(0xffffffffu, mt0, 1));
            mt0 = fmaxf(mt0, __shfl_xor_sync(0xffffffffu, mt0, 2));
            mt1 = fmaxf(mt1, __shfl_xor_sync(0xffffffffu, mt1, 1));
            mt1 = fmaxf(mt1, __shfl_xor_sync(0xffffffffu, mt1, 2));
            const float mn0 = fmaxf(m0, mt0), mn1 = fmaxf(m1, mt1);
            const float a0 = exp2f(m0 - mn0), a1 = exp2f(m1 - mn1);
            m0 = mn0; m1 = mn1;
            float ls0 = 0.f, ls1 = 0.f;
#pragma unroll
            for (int j = 0; j < 8; j++)
#pragma unroll
                for (int c = 0; c < 2; c++) {
                    float p = exp2f(s[j][c] - mn0);
                    s[j][c] = p; ls0 += p;
                    float p2 = exp2f(s[j][2 + c] - mn1);
                    s[j][2 + c] = p2; ls1 += p2;
                }
            ls0 += __shfl_xor_sync(0xffffffffu, ls0, 1);
            ls0 += __shfl_xor_sync(0xffffffffu, ls0, 2);
            ls1 += __shfl_xor_sync(0xffffffffu, ls1, 1);
            ls1 += __shfl_xor_sync(0xffffffffu, ls1, 2);
            l0 = l0 * a0 + ls0;
            l1 = l1 * a1 + ls1;
#pragma unroll
            for (int j = 0; j < 8; j++) {
                o[j][0] *= a0; o[j][1] *= a0;
                o[j][2] *= a1; o[j][3] *= a1;
            }

            // O += P V (P single fp16)
#pragma unroll
            for (int kc = 0; kc < 4; kc++) {
                uint32_t ph[4];
                ph[0] = pack2s(s[2 * kc][0],     s[2 * kc][1]);
                ph[1] = pack2s(s[2 * kc][2],     s[2 * kc][3]);
                ph[2] = pack2s(s[2 * kc + 1][0], s[2 * kc + 1][1]);
                ph[3] = pack2s(s[2 * kc + 1][2], s[2 * kc + 1][3]);
                const uint32_t rowb = (uint32_t)((kc * 16 + (lane & 15)) * 128 + ((lane >> 4) << 4));
#pragma unroll
                for (int dg = 0; dg < 4; dg++) {
                    uint32_t ad = SWZ128(rowb + dg * 32);
                    uint32_t vh4[4];
                    LDSM4T(vh4, vbuf + ad);
                    MMAH(o[2 * dg],     ph, vh4[0], vh4[1]);
                    MMAH(o[2 * dg + 1], ph, vh4[2], vh4[3]);
                }
            }
        }

        __syncthreads();
        if (it + 2 < nt) issue_kv(it & 1, (kt_lo + it + 2) * 64);
    }

    const float inv0 = 1.f / l0, inv1 = 1.f / l1;
    const size_t e0 = ((size_t)(b * SS) + r0) * D_MODEL + h * DK + (lane & 3) * 2;
    const size_t e1 = e0 + 8 * D_MODEL;
#pragma unroll
    for (int j = 0; j < 8; j++) {
        *(uint32_t*)(g_aoh + e0 + j * 8) = pack2s(o[j][0] * inv0, o[j][1] * inv0);
        *(uint32_t*)(g_aoh + e1 + j * 8) = pack2s(o[j][2] * inv1, o[j][3] * inv1);
    }
}

// ---------------------------------------------------------------------------

extern "C" void kernel_launch(void* const* d_in, const int* in_sizes, int n_in,
                              void* d_out, int out_size)
{
    const float* x  = (const float*)d_in[0];
    const float* Wq = (const float*)d_in[1];
    const float* bq = (const float*)d_in[2];
    const float* Wk = (const float*)d_in[3];
    const float* bk = (const float*)d_in[4];
    const float* Wv = (const float*)d_in[5];
    const float* bv = (const float*)d_in[6];
    const float* Wo = (const float*)d_in[7];
    const float* bo = (const float*)d_in[8];
    float* out = (float*)d_out;

    const int GSM = 4 * 16384 + 1024;           // 66560 B/CTA -> 2 CTAs/SM
    const int ASM = 8192 + 2 * 16384 + 1024;    // 41984 B/CTA
    static bool attr_done = false;
    if (!attr_done) {
        cudaFuncSetAttribute(tc_gemm, cudaFuncAttributeMaxDynamicSharedMemorySize, GSM);
        cudaFuncSetAttribute(fa_attn, cudaFuncAttributeMaxDynamicSharedMemorySize, ASM);
        attr_done = true;
    }

    const int NCVT = NX4 + 4 * NW4;
    cvt_all<<<(NCVT + 255) / 256, 256>>>((const float4*)x, (const float4*)Wq,
                                         (const float4*)Wk, (const float4*)Wv,
                                         (const float4*)Wo);

    tc_gemm<<<dim3(D_MODEL / 128, M_TOT / 128, 3), 128, GSM>>>(0, bq, bk, bv, nullptr);
    fa_attn<<<dim3(SS / 64, NH, BB), 128, ASM>>>();
    tc_gemm<<<dim3(D_MODEL / 128, M_TOT / 128, 1), 128, GSM>>>(1, bo, bo, bo, out);
}